// round 15
// baseline (speedup 1.0000x reference)
#include <cuda_runtime.h>
#include <cstdint>

#define MAXN 10000
#define KNBR 16
#define MAXE (MAXN * KNBR)
#define FDIM 64
#define HDIM 128

typedef unsigned long long u64;
typedef unsigned int u32;
typedef unsigned short u16;

// ---------------- scratch (no allocations allowed) ----------------
__device__ int   g_nidx[MAXE];
__device__ float g_dsq [MAXE];
__device__ int   g_selfi[MAXN];
__device__ float g_w[MAXE];
__device__ __align__(16) float g_sx[MAXN];
__device__ __align__(16) float g_sy[MAXN];
__device__ __align__(16) float g_sz[MAXN];
__device__ __align__(16) float g_sn[MAXN];
__device__ __align__(16) float gW1s[64 * 128];
__device__ __align__(16) float gNself[(size_t)(MAXN + 128) * 64];
__device__ __align__(16) float gYself[(size_t)(MAXN + 128) * 128];
// bf16 hi/lo operand images, plain row-major
__device__ __align__(16) u16 gB2h[(size_t)MAXE * 128];
__device__ __align__(16) u16 gB2l[(size_t)MAXE * 128];
__device__ __align__(16) u16 gC3h[(size_t)MAXE * 128];
__device__ __align__(16) u16 gC3l[(size_t)MAXE * 128];
// node-path images
__device__ __align__(16) u16 gNinh[(size_t)(MAXN + 128) * 192];
__device__ __align__(16) u16 gNinl[(size_t)(MAXN + 128) * 192];
__device__ __align__(16) u16 gXn1h[(size_t)(MAXN + 128) * 128];
__device__ __align__(16) u16 gXn1l[(size_t)(MAXN + 128) * 128];
// weight images, transposed: Wt[n][k]
__device__ __align__(16) u16 gWh1[128 * 64],  gWl1[128 * 64];
__device__ __align__(16) u16 gWh2[128 * 128], gWl2[128 * 128];
__device__ __align__(16) u16 gWh3[128 * 128], gWl3[128 * 128];
__device__ __align__(16) u16 gWn1h[128 * 192], gWn1l[128 * 192];
__device__ __align__(16) u16 gWn2h[128 * 128], gWn2l[128 * 128];

// ---------------- generic helpers ----------------
__device__ __forceinline__ u64 pk2(float lo, float hi) {
    u64 r; asm("mov.b64 %0, {%1, %2};" : "=l"(r) : "f"(lo), "f"(hi)); return r;
}
__device__ __forceinline__ void upk2(u64 v, float& lo, float& hi) {
    asm("mov.b64 {%0, %1}, %2;" : "=f"(lo), "=f"(hi) : "l"(v));
}
__device__ __forceinline__ void fma2(u64& d, u64 a, u64 b) {
    asm("fma.rn.f32x2 %0, %1, %2, %0;" : "+l"(d) : "l"(a), "l"(b));
}
__device__ __forceinline__ u64 mk_key(float d, int j) {
    u64 k; asm("mov.b64 %0, {%1, %2};" : "=l"(k) : "r"(j), "r"(__float_as_uint(d)));
    return k;
}
__device__ __forceinline__ float selu_f(float x) {
    const float sc = 1.0507009873554805f;
    const float sa = 1.7580993408473766f;  // sc * alpha
    float e   = __expf(x);
    float neg = __fmaf_rn(sa, e, -sa);
    return x > 0.f ? sc * x : neg;
}
__device__ __forceinline__ void cpa16(u32 dst, const void* src) {
    asm volatile("cp.async.cg.shared.global [%0], [%1], 16;" :: "r"(dst), "l"(src));
}
__device__ __forceinline__ u32 smem_u32(const void* p) {
    u32 a; asm("{ .reg .u64 t; cvta.to.shared.u64 t, %1; cvt.u32.u64 %0, t; }" : "=r"(a) : "l"(p));
    return a;
}
// pack two f32 -> bf16x2 (low half = x0, high half = x1)
__device__ __forceinline__ u32 pack2bf(float x0, float x1) {
    u32 r; asm("cvt.rn.bf16x2.f32 %0, %1, %2;" : "=r"(r) : "f"(x1), "f"(x0)); return r;
}
// bf16 mma m16n8k16, f32 accumulate
__device__ __forceinline__ void hmma(float (&d)[4], u32 a0, u32 a1, u32 a2, u32 a3,
                                     u32 b0, u32 b1) {
    asm volatile(
        "mma.sync.aligned.m16n8k16.row.col.f32.bf16.bf16.f32 "
        "{%0,%1,%2,%3}, {%4,%5,%6,%7}, {%8,%9}, {%0,%1,%2,%3};"
        : "+f"(d[0]), "+f"(d[1]), "+f"(d[2]), "+f"(d[3])
        : "r"(a0), "r"(a1), "r"(a2), "r"(a3), "r"(b0), "r"(b1));
}

// ---------------- prep: SoA coords + norms ----------------
__global__ void prep_kernel(const float* __restrict__ coords, int N) {
    int i = blockIdx.x * 256 + threadIdx.x;
    if (i < N) {
        float x = coords[3 * i + 0];
        float y = coords[3 * i + 1];
        float z = coords[3 * i + 2];
        g_sx[i] = x; g_sy[i] = y; g_sz[i] = z;
        g_sn[i] = __fmaf_rn(z, z, __fmaf_rn(y, y, __fmul_rn(x, x)));
    }
}

// ---------------- KNN: warp-distributed sorted top-17, scalar d2 + any-ballot
#define KNN_WARPS 8
#define KSENT 0x7F800000FFFFFFFFull   // +inf distance sentinel

__global__ void __launch_bounds__(256)
knn_kernel(const int* __restrict__ rs, int nrs, int N,
           float* __restrict__ out_nidx_f, float* __restrict__ out_d)
{
    const int w    = threadIdx.x >> 5;
    const int lane = threadIdx.x & 31;
    const int row  = blockIdx.x * KNN_WARPS + w;
    (void)w;
    if (row >= N) return;

    int s0 = 0, s1 = N;
    for (int s = 0; s + 1 < nrs; ++s) {
        int a_ = rs[s], b_ = rs[s + 1];
        if (a_ <= row && row < b_) { s0 = a_; s1 = b_; }
    }

    const float xi = g_sx[row], yi = g_sy[row], zi = g_sz[row], ni = g_sn[row];

    u64 L    = KSENT;                           // warp-distributed list entry
    u64 curT = KSENT;                           // current 17th-smallest (L[16])
    float Tf = __uint_as_float(0x7F800000u);    // +inf

    auto insert_key = [&](u64 k) {
        unsigned bal = __ballot_sync(0xffffffffu, L <= k);
        int pos = __popc(bal);                  // <= 16 since k < L[16]
        u64 up = __shfl_up_sync(0xffffffffu, L, 1);
        if (lane == pos)                 L = k;
        else if (lane > pos && lane < 17) L = up;
        curT = __shfl_sync(0xffffffffu, L, 16);
        Tf = __uint_as_float((u32)(curT >> 32));
    };

    auto commit = [&](u64 key, bool pass) {
        unsigned pb = __ballot_sync(0xffffffffu, pass);
        while (pb) {
            int src = __ffs(pb) - 1; pb &= pb - 1;
            u64 k = __shfl_sync(0xffffffffu, key, src);
            if (k < curT) insert_key(k);        // warp-uniform branch
        }
    };

    auto d2_of = [&](float xj, float yj, float zj, float nj) {
        float dot = __fmul_rn(xi, xj);
        dot = __fmaf_rn(yi, yj, dot);
        dot = __fmaf_rn(zi, zj, dot);
        float nn = __fadd_rn(ni, nj);
        float d2 = __fmaf_rn(-2.f, dot, nn);
        return fmaxf(d2, 0.f);
    };

    // ---- prolog: align to 4 ----
    int jb = (s0 + 3) & ~3;
    if (jb > s1) jb = s1;
    {
        int pre = jb - s0;                      // 0..3
        bool act = lane < pre;
        int j = s0 + (act ? lane : 0);
        float d2 = d2_of(g_sx[j], g_sy[j], g_sz[j], g_sn[j]);
        u64 key = mk_key(d2, j);
        commit(key, act && d2 <= Tf);
    }

    const int nquad = (s1 - jb) >> 2;
    const int rem   = (s1 - jb) & 3;

    // ---- main quad loop: scalar d2 (proven) + single any-ballot per quad ----
    for (int q0 = 0; q0 < nquad; q0 += 32) {
        int q = q0 + lane;
        bool act = q < nquad;
        int j = jb + 4 * (act ? q : 0);
        float4 X  = *(const float4*)(g_sx + j);
        float4 Y  = *(const float4*)(g_sy + j);
        float4 Z  = *(const float4*)(g_sz + j);
        float4 Nn = *(const float4*)(g_sn + j);
        float d0 = d2_of(X.x, Y.x, Z.x, Nn.x);
        float d1 = d2_of(X.y, Y.y, Z.y, Nn.y);
        float d2v = d2_of(X.z, Y.z, Z.z, Nn.z);
        float d3 = d2_of(X.w, Y.w, Z.w, Nn.w);
        bool p0 = act && d0 <= Tf;
        bool p1 = act && d1 <= Tf;
        bool p2 = act && d2v <= Tf;
        bool p3 = act && d3 <= Tf;
        unsigned any = __ballot_sync(0xffffffffu, p0 | p1 | p2 | p3);
        if (any) {                              // rare, warp-uniform
            commit(mk_key(d0, j),      p0);
            commit(mk_key(d1, j + 1),  p1);
            commit(mk_key(d2v, j + 2), p2);
            commit(mk_key(d3, j + 3),  p3);
        }
    }

    // ---- remainder ----
    if (rem) {
        bool act = lane < rem;
        int j = jb + 4 * nquad + (act ? lane : 0);
        float d2 = d2_of(g_sx[j], g_sy[j], g_sz[j], g_sn[j]);
        u64 key = mk_key(d2, j);
        commit(key, act && d2 <= Tf);
    }

    // ---- emit: lanes 0..16 hold the sorted top-17 ----
    if (lane < 17) {
        u32 jj = (u32)(L & 0xffffffffu);
        float dd = __uint_as_float((u32)(L >> 32));
        if (lane == 0) {
            g_selfi[row] = (int)jj;
        } else {
            int t = lane - 1;
            g_nidx[row * KNBR + t] = (int)jj;
            g_dsq [row * KNBR + t] = dd;
            out_nidx_f[row * KNBR + t] = (float)(int)jj;
            out_d    [row * KNBR + t] = dd;
        }
    }
}

// ---------------- weight / image prep (merged) ----------------
__device__ __forceinline__ void wimg_body(const float* __restrict__ W, int K, int roff,
                                          u16* __restrict__ hi, u16* __restrict__ lo,
                                          int idx) {
    if (idx < K * 128) {
        int n = idx / K, k = idx - n * K;
        float v = W[(roff + k) * 128 + n];
        u32 ph = pack2bf(v, 0.f);
        float vh = __uint_as_float(ph << 16);
        u32 pl = pack2bf(v - vh, 0.f);
        hi[idx] = (u16)(ph & 0xffffu);
        lo[idx] = (u16)(pl & 0xffffu);
    }
}

// blocks [0,32): gW1s; [32,64): We1 img; [64,128): We2 img; [128,192): Wc1 img
__global__ void prep_weights_edge(const float* __restrict__ We1,
                                  const float* __restrict__ We2,
                                  const float* __restrict__ Wc1) {
    int b = blockIdx.x, tid = threadIdx.x;
    if (b < 32) {
        int i = b * 256 + tid;
        int k = i >> 7, n = i & 127;
        gW1s[i] = We1[(1 + k) * 128 + n];
    } else if (b < 64) {
        wimg_body(We1, 64, 65, gWh1, gWl1, (b - 32) * 256 + tid);
    } else if (b < 128) {
        wimg_body(We2, 128, 0, gWh2, gWl2, (b - 64) * 256 + tid);
    } else {
        wimg_body(Wc1, 128, 0, gWh3, gWl3, (b - 128) * 256 + tid);
    }
}

// blocks [0,96): Wn1 img (K=192); [96,160): Wn2 img
__global__ void prep_weights_node(const float* __restrict__ Wn1,
                                  const float* __restrict__ Wn2) {
    int b = blockIdx.x, tid = threadIdx.x;
    if (b < 96) wimg_body(Wn1, 192, 0, gWn1h, gWn1l, b * 256 + tid);
    else        wimg_body(Wn2, 128, 0, gWn2h, gWn2l, (b - 96) * 256 + tid);
}

// gNself[n] = h[self(n)] fp32 (for Yself stage); node-input image cols 128:192 = h_self hi/lo
__global__ void build_ns(const float* __restrict__ h, int N) {
    int idx = blockIdx.x * 256 + threadIdx.x;
    if (idx < N * 16) {
        int n = idx >> 4, q = idx & 15;
        float4 v = *(const float4*)(h + (size_t)g_selfi[n] * FDIM + q * 4);
        *(float4*)(gNself + (size_t)n * 64 + q * 4) = v;
        u32 ph0 = pack2bf(v.x, v.y);
        u32 ph1 = pack2bf(v.z, v.w);
        float a0 = __uint_as_float(ph0 << 16), a1 = __uint_as_float(ph0 & 0xffff0000u);
        float a2 = __uint_as_float(ph1 << 16), a3 = __uint_as_float(ph1 & 0xffff0000u);
        u32 pl0 = pack2bf(v.x - a0, v.y - a1);
        u32 pl1 = pack2bf(v.z - a2, v.w - a3);
        size_t off = (size_t)n * 192 + 128 + q * 4;
        *(u32*)(gNinh + off)     = ph0;  *(u32*)(gNinh + off + 2) = ph1;
        *(u32*)(gNinl + off)     = pl0;  *(u32*)(gNinl + off + 2) = pl1;
    }
}

// coords_new = coords + mean_k((c_i - c_j) * w)
__global__ void coords_kernel(const float* __restrict__ coords,
                              float* __restrict__ cout, int N) {
    int n = blockIdx.x * 256 + threadIdx.x;
    if (n < N) {
        float cx = coords[n * 3 + 0];
        float cy = coords[n * 3 + 1];
        float cz = coords[n * 3 + 2];
        float sx = 0.f, sy = 0.f, sz = 0.f;
#pragma unroll
        for (int k = 0; k < 16; ++k) {
            int j = g_nidx[n * 16 + k];
            float wv = g_w[n * 16 + k];
            sx += (cx - coords[j * 3 + 0]) * wv;
            sy += (cy - coords[j * 3 + 1]) * wv;
            sz += (cz - coords[j * 3 + 2]) * wv;
        }
        cout[n * 3 + 0] = cx + sx * 0.0625f;
        cout[n * 3 + 1] = cy + sy * 0.0625f;
        cout[n * 3 + 2] = cz + sz * 0.0625f;
    }
}

// ---------------- R5 FFMA staged GEMM (Yself; proven) ----------------
__device__ __forceinline__ void mma_chunk8(const float* __restrict__ As,
                                           const float* __restrict__ Ws,
                                           u64 (&acc)[8][4], int m0, int n0)
{
#pragma unroll
    for (int s = 0; s < 4; ++s) {
        float4 av[8];
#pragma unroll
        for (int i = 0; i < 8; ++i)
            av[i] = *(const float4*)(As + (m0 + i) * 16 + s * 4);
#pragma unroll
        for (int r = 0; r < 4; ++r) {
            const float* wr = Ws + (s * 4 + r) * 128 + n0;
            ulonglong2 b0 = *(const ulonglong2*)wr;
            ulonglong2 b1 = *(const ulonglong2*)(wr + 4);
#pragma unroll
            for (int i = 0; i < 8; ++i) {
                float a_ = (r == 0) ? av[i].x : (r == 1) ? av[i].y : (r == 2) ? av[i].z : av[i].w;
                u64 aa = pk2(a_, a_);
                fma2(acc[i][0], aa, b0.x);
                fma2(acc[i][1], aa, b0.y);
                fma2(acc[i][2], aa, b1.x);
                fma2(acc[i][3], aa, b1.y);
            }
        }
    }
}

template<int KCH, int EPI>   // EPI: 0 = selu+store, 1 = store
__global__ void __launch_bounds__(256, 2)
gemm_stage(const float* __restrict__ A, int lda,
           const float* __restrict__ Wg, const float* __restrict__ bias,
           float* __restrict__ O, int ldo, int M)
{
    extern __shared__ float sm[];
    float* Ws = sm;
    float* As = Ws + KCH * 2048;
    float* sb = As + 4096;

    const int tid = threadIdx.x;
    const int tx = tid & 15, ty = tid >> 4;
    const int n0 = tx * 8,   m0 = ty * 8;
    const long row0 = (long)blockIdx.x * 128;

    for (int i = tid; i < KCH * 512; i += 256)
        ((float4*)Ws)[i] = ((const float4*)Wg)[i];
    if (tid < 32) ((float4*)sb)[tid] = ((const float4*)bias)[tid];

    const u32 asu = (u32)__cvta_generic_to_shared(As);
    auto issue = [&](int c, int bufsel) {
        const float* srcbase = A + row0 * lda + c * 16;
        u32 d0 = asu + (u32)(bufsel * 2048 * 4);
        int q = tid;   int r = q >> 2, kq = q & 3;
        cpa16(d0 + (u32)((r * 16 + kq * 4) * 4), srcbase + (long)r * lda + kq * 4);
        q = tid + 256; r = q >> 2; kq = q & 3;
        cpa16(d0 + (u32)((r * 16 + kq * 4) * 4), srcbase + (long)r * lda + kq * 4);
        asm volatile("cp.async.commit_group;");
    };

    issue(0, 0);
    __syncthreads();

    u64 acc[8][4];
#pragma unroll
    for (int i = 0; i < 8; ++i)
#pragma unroll
        for (int j = 0; j < 4; ++j)
            acc[i][j] = pk2(sb[n0 + 2 * j], sb[n0 + 2 * j + 1]);

#pragma unroll 1
    for (int c = 0; c < KCH; ++c) {
        if (c + 1 < KCH) {
            issue(c + 1, (c + 1) & 1);
            asm volatile("cp.async.wait_group 1;");
        } else {
            asm volatile("cp.async.wait_group 0;");
        }
        __syncthreads();
        mma_chunk8(As + (c & 1) * 2048, Ws + c * 2048, acc, m0, n0);
        __syncthreads();
    }

#pragma unroll
    for (int i = 0; i < 8; ++i) {
        long grow = row0 + m0 + i;
        if (grow < M) {
            float o[8];
#pragma unroll
            for (int j = 0; j < 4; ++j) upk2(acc[i][j], o[2 * j], o[2 * j + 1]);
            if (EPI == 0) {
#pragma unroll
                for (int j = 0; j < 8; ++j) o[j] = selu_f(o[j]);
            }
            *(float4*)(O + grow * ldo + n0)     = make_float4(o[0], o[1], o[2], o[3]);
            *(float4*)(O + grow * ldo + n0 + 4) = make_float4(o[4], o[5], o[6], o[7]);
        }
    }
}

// ---------------- fused edge stage 1: gather h_neig + HMMA (KK=64) ----------
__global__ void __launch_bounds__(256)
mma_stage1(const float* __restrict__ h,
           const u16* __restrict__ Wih, const u16* __restrict__ Wil,
           const float* __restrict__ aux,     // We1 row 0
           const float* __restrict__ yselfg,
           const float* __restrict__ dsqg,
           u16* __restrict__ outHi, u16* __restrict__ outLo)
{
    constexpr int KK = 64;
    constexpr int SA = KK + 8;
    extern __shared__ u16 smu[];
    u16* sAh = smu;
    u16* sAl = sAh + 128 * SA;
    u16* sWh = sAl + 128 * SA;
    u16* sWl = sWh + 128 * SA;

    const int tid  = threadIdx.x;
    const int w    = tid >> 5;
    const int lane = tid & 31;
    const int g    = lane >> 2;
    const int tig  = lane & 3;
    const int tile = blockIdx.x;

    // ---- W copies via cp.async (overlap with A gather) ----
    const u32 sb = smem_u32(smu);
    for (int i = tid; i < 1024; i += 256) {        // 128 rows x 8 chunks
        int r = i >> 3, c = i & 7;
        u32 dof = (u32)((r * SA + c * 8) * 2);
        u32 sof = (u32)((r * KK + c * 8) * 2);
        cpa16(sb + 2 * 128 * SA * 2 + dof, (const char*)Wih + sof);
        cpa16(sb + 3 * 128 * SA * 2 + dof, (const char*)Wil + sof);
    }
    asm volatile("cp.async.commit_group;");

    // ---- A gather: 2 threads per row, 32 floats each ----
    {
        int r  = tid >> 1;
        int hf = tid & 1;
        int nb = g_nidx[tile * 128 + r];
        const float* hr = h + (size_t)nb * FDIM + hf * 32;
        u16* dh = sAh + r * SA + hf * 32;
        u16* dl = sAl + r * SA + hf * 32;
#pragma unroll
        for (int c = 0; c < 4; ++c) {
            float4 f0 = *(const float4*)(hr + c * 8);
            float4 f1 = *(const float4*)(hr + c * 8 + 4);
            float x[8] = {f0.x, f0.y, f0.z, f0.w, f1.x, f1.y, f1.z, f1.w};
            u32 hp[4], lp[4];
#pragma unroll
            for (int q = 0; q < 4; ++q) {
                u32 ph = pack2bf(x[2 * q], x[2 * q + 1]);
                float h0 = __uint_as_float(ph << 16);
                float h1 = __uint_as_float(ph & 0xffff0000u);
                hp[q] = ph;
                lp[q] = pack2bf(x[2 * q] - h0, x[2 * q + 1] - h1);
            }
            *(uint4*)(dh + c * 8) = make_uint4(hp[0], hp[1], hp[2], hp[3]);
            *(uint4*)(dl + c * 8) = make_uint4(lp[0], lp[1], lp[2], lp[3]);
        }
    }

    // ---- accumulator init (zero; bias folded via Yself) ----
    float acc[16][4];
#pragma unroll
    for (int nt = 0; nt < 16; ++nt) {
        acc[nt][0] = 0.f; acc[nt][1] = 0.f; acc[nt][2] = 0.f; acc[nt][3] = 0.f;
    }

    asm volatile("cp.async.wait_group 0;");
    __syncthreads();

    const int rA0 = (16 * w + g) * SA;
    const int rA1 = (16 * w + g + 8) * SA;

#pragma unroll
    for (int k0 = 0; k0 < KK; k0 += 16) {
        const int co = k0 + 2 * tig;
        u32 ah0 = *(const u32*)(sAh + rA0 + co);
        u32 ah1 = *(const u32*)(sAh + rA1 + co);
        u32 ah2 = *(const u32*)(sAh + rA0 + co + 8);
        u32 ah3 = *(const u32*)(sAh + rA1 + co + 8);
        u32 al0 = *(const u32*)(sAl + rA0 + co);
        u32 al1 = *(const u32*)(sAl + rA1 + co);
        u32 al2 = *(const u32*)(sAl + rA0 + co + 8);
        u32 al3 = *(const u32*)(sAl + rA1 + co + 8);
#pragma unroll
        for (int nt = 0; nt < 16; ++nt) {
            const int rb = (nt * 8 + g) * SA + co;
            u32 bh0 = *(const u32*)(sWh + rb);
            u32 bh1 = *(const u32*)(sWh + rb + 8);
            u32 bl0 = *(const u32*)(sWl + rb);
            u32 bl1 = *(const u32*)(sWl + rb + 8);
            hmma(acc[nt], ah0, ah1, ah2, ah3, bh0, bh1);
            hmma(acc[nt], ah0, ah1, ah2, ah3, bl0, bl1);
            hmma(acc[nt], al0, al1, al2, al3, bh0, bh1);
        }
    }

    // ---- epilogue (EPI1) ----
    const int node = tile * 8 + w;
    float dsq_r[2];
    dsq_r[0] = dsqg[(size_t)tile * 128 + 16 * w + g];
    dsq_r[1] = dsqg[(size_t)tile * 128 + 16 * w + g + 8];

#pragma unroll
    for (int nt = 0; nt < 16; ++nt) {
        const int col = nt * 8 + 2 * tig;
        float2 t = *(const float2*)(yselfg + (size_t)node * 128 + col);
        float2 u = *(const float2*)(aux + col);
#pragma unroll
        for (int r = 0; r < 2; ++r) {
            const int row = 16 * w + g + 8 * r;
            const size_t gr = (size_t)tile * 128 + row;
            float v0 = acc[nt][2 * r]     + t.x + dsq_r[r] * u.x;
            float v1 = acc[nt][2 * r + 1] + t.y + dsq_r[r] * u.y;
            v0 = selu_f(v0); v1 = selu_f(v1);
            u32 ph = pack2bf(v0, v1);
            float h0 = __uint_as_float(ph << 16);
            float h1 = __uint_as_float(ph & 0xffff0000u);
            u32 pl = pack2bf(v0 - h0, v1 - h1);
            *(u32*)((char*)outHi + (gr * 128 + col) * 2) = ph;
            *(u32*)((char*)outLo + (gr * 128 + col) * 2) = pl;
        }
    }
}

// ---------------- HMMA GEMM stage (bf16 hi/lo 3-term split) ----------------
// EPI: 0 = bias+selu, emit bf16 images                       (node stage 1)
//      2 = bias+selu, emit bf16 images, e_sum -> esum images (edge stage 2)
//      3 = bias+selu, dot with Wc2 -> g_w                    (edge stage 3)
//      5 = bias, fp32 store (bounds-checked)                 (node stage 2)
template<int KK, int EPI>
__global__ void __launch_bounds__(256)
mma_stage(const u16* __restrict__ Aih, const u16* __restrict__ Ail,
          const u16* __restrict__ Wih, const u16* __restrict__ Wil,
          const float* __restrict__ biasg,
          const float* __restrict__ aux,     // EPI3: Wc2
          const float* __restrict__ bc2g,    // EPI3
          u16* __restrict__ outHi, u16* __restrict__ outLo,   // EPI 0/2
          u16* __restrict__ esumHi, u16* __restrict__ esumLo, // EPI2
          float* __restrict__ woutg,         // EPI3
          float* __restrict__ Og, int M)     // EPI5
{
    constexpr int SA = KK + 8;
    extern __shared__ u16 smu[];
    u16* sAh = smu;
    u16* sAl = sAh + 128 * SA;
    u16* sWh = sAl + 128 * SA;
    u16* sWl = sWh + 128 * SA;

    const int tid  = threadIdx.x;
    const int w    = tid >> 5;
    const int lane = tid & 31;
    const int g    = lane >> 2;
    const int tig  = lane & 3;
    const int tile = blockIdx.x;

    // ---- async copies: two commit groups, split by K-halves ----
    constexpr int CPR = KK / 8;
    constexpr int HC  = CPR / 2;
    const u32 sb = smem_u32(smu);
    {
        const char* sa = (const char*)Aih + (size_t)tile * 128 * KK * 2;
        const char* sl = (const char*)Ail + (size_t)tile * 128 * KK * 2;
#pragma unroll
        for (int hh = 0; hh < 2; ++hh) {
            for (int i = tid; i < 128 * HC; i += 256) {
                int r = i / HC, c = hh * HC + (i - (i / HC) * HC);
                u32 dof = (u32)((r * SA + c * 8) * 2);
                u32 sof = (u32)((r * KK + c * 8) * 2);
                cpa16(sb + dof,                   sa + sof);
                cpa16(sb + 128 * SA * 2 + dof,    sl + sof);
                cpa16(sb + 2 * 128 * SA * 2 + dof, (const char*)Wih + sof);
                cpa16(sb + 3 * 128 * SA * 2 + dof, (const char*)Wil + sof);
            }
            asm volatile("cp.async.commit_group;");
        }
    }

    // ---- accumulator init (bias) ----
    float acc[16][4];
#pragma unroll
    for (int nt = 0; nt < 16; ++nt) {
        float b0 = __ldg(biasg + nt * 8 + 2 * tig);
        float b1 = __ldg(biasg + nt * 8 + 2 * tig + 1);
        acc[nt][0] = b0; acc[nt][1] = b1; acc[nt][2] = b0; acc[nt][3] = b1;
    }

    const int rA0 = (16 * w + g) * SA;
    const int rA1 = (16 * w + g + 8) * SA;

    auto mma_k = [&](int k0) {
        const int co = k0 + 2 * tig;
        u32 ah0 = *(const u32*)(sAh + rA0 + co);
        u32 ah1 = *(const u32*)(sAh + rA1 + co);
        u32 ah2 = *(const u32*)(sAh + rA0 + co + 8);
        u32 ah3 = *(const u32*)(sAh + rA1 + co + 8);
        u32 al0 = *(const u32*)(sAl + rA0 + co);
        u32 al1 = *(const u32*)(sAl + rA1 + co);
        u32 al2 = *(const u32*)(sAl + rA0 + co + 8);
        u32 al3 = *(const u32*)(sAl + rA1 + co + 8);
#pragma unroll
        for (int nt = 0; nt < 16; ++nt) {
            const int rb = (nt * 8 + g) * SA + co;
            u32 bh0 = *(const u32*)(sWh + rb);
            u32 bh1 = *(const u32*)(sWh + rb + 8);
            u32 bl0 = *(const u32*)(sWl + rb);
            u32 bl1 = *(const u32*)(sWl + rb + 8);
            hmma(acc[nt], ah0, ah1, ah2, ah3, bh0, bh1);
            hmma(acc[nt], ah0, ah1, ah2, ah3, bl0, bl1);
            hmma(acc[nt], al0, al1, al2, al3, bh0, bh1);
        }
    };

    asm volatile("cp.async.wait_group 1;");
    __syncthreads();
#pragma unroll
    for (int k0 = 0; k0 < KK / 2; k0 += 16) mma_k(k0);

    asm volatile("cp.async.wait_group 0;");
    __syncthreads();
#pragma unroll
    for (int k0 = KK / 2; k0 < KK; k0 += 16) mma_k(k0);

    // ---- epilogue ----
    const int node = tile * 8 + w;
    float pr[2] = {0.f, 0.f};

#pragma unroll
    for (int nt = 0; nt < 16; ++nt) {
        const int col = nt * 8 + 2 * tig;
        float wv0 = 0.f, wv1 = 0.f;
        if (EPI == 3) {
            float2 u = *(const float2*)(aux + col);
            wv0 = u.x; wv1 = u.y;
        }
        float ps0 = 0.f, ps1 = 0.f;
#pragma unroll
        for (int r = 0; r < 2; ++r) {
            const int row = 16 * w + g + 8 * r;
            const size_t gr = (size_t)tile * 128 + row;
            float v0 = acc[nt][2 * r];
            float v1 = acc[nt][2 * r + 1];
            if (EPI != 5) { v0 = selu_f(v0); v1 = selu_f(v1); }
            if (EPI == 0 || EPI == 2) {
                u32 ph = pack2bf(v0, v1);
                float h0 = __uint_as_float(ph << 16);
                float h1 = __uint_as_float(ph & 0xffff0000u);
                u32 pl = pack2bf(v0 - h0, v1 - h1);
                *(u32*)((char*)outHi + (gr * 128 + col) * 2) = ph;
                *(u32*)((char*)outLo + (gr * 128 + col) * 2) = pl;
            }
            if (EPI == 2) { ps0 += v0; ps1 += v1; }
            if (EPI == 3) { pr[r] = fmaf(v0, wv0, fmaf(v1, wv1, pr[r])); }
            if (EPI == 5) {
                if ((long)gr < M)
                    *(float2*)(Og + gr * 128 + col) = make_float2(v0, v1);
            }
        }
        if (EPI == 2) {
            ps0 += __shfl_xor_sync(0xffffffffu, ps0, 4);
            ps0 += __shfl_xor_sync(0xffffffffu, ps0, 8);
            ps0 += __shfl_xor_sync(0xffffffffu, ps0, 16);
            ps1 += __shfl_xor_sync(0xffffffffu, ps1, 4);
            ps1 += __shfl_xor_sync(0xffffffffu, ps1, 8);
            ps1 += __shfl_xor_sync(0xffffffffu, ps1, 16);
            if (g == 0) {
                u32 ph = pack2bf(ps0, ps1);
                float h0 = __uint_as_float(ph << 16);
                float h1 = __uint_as_float(ph & 0xffff0000u);
                u32 pl = pack2bf(ps0 - h0, ps1 - h1);
                size_t off = ((size_t)node * 192 + col) * 2;
                *(u32*)((char*)esumHi + off) = ph;
                *(u32*)((char*)esumLo + off) = pl;
            }
        }
    }
    if (EPI == 3) {
        const float bc = bc2g[0];
#pragma unroll
        for (int r = 0; r < 2; ++r) {
            float p = pr[r];
            p += __shfl_xor_sync(0xffffffffu, p, 1);
            p += __shfl_xor_sync(0xffffffffu, p, 2);
            if (tig == 0)
                woutg[(size_t)tile * 128 + 16 * w + g + 8 * r] = p + bc;
        }
    }
}

// ---------------- launch ----------------
extern "C" void kernel_launch(void* const* d_in, const int* in_sizes, int n_in,
                              void* d_out, int out_size)
{
    const float* h      = (const float*)d_in[0];
    const float* coords = (const float*)d_in[1];
    const int*   rs     = (const int*)  d_in[2];
    const float* We1 = (const float*)d_in[3];
    const float* be1 = (const float*)d_in[4];
    const float* We2 = (const float*)d_in[5];
    const float* be2 = (const float*)d_in[6];
    const float* Wc1 = (const float*)d_in[7];
    const float* bc1 = (const float*)d_in[8];
    const float* Wc2 = (const float*)d_in[9];
    const float* bc2 = (const float*)d_in[10];
    const float* Wn1 = (const float*)d_in[11];
    const float* bn1 = (const float*)d_in[12];
    const float* Wn2 = (const float*)d_in[13];
    const float* bn2 = (const float*)d_in[14];

    const int N   = in_sizes[1] / 3;
    const int nrs = in_sizes[2];
    const int E   = N * KNBR;
    const int tiles  = E / 128;
    const int ntiles = (N + 127) / 128;

    float* out        = (float*)d_out;               // [N,128]
    float* coords_out = out + (size_t)N * HDIM;      // [N,3]
    float* out_nidx   = coords_out + (size_t)N * 3;  // [N,16]
    float* out_d      = out_nidx + (size_t)N * KNBR; // [N,16]

    float *pW1s, *pNself, *pYself, *pw, *pdsq;
    u16 *pB2h, *pB2l, *pC3h, *pC3l;
    u16 *pWh1, *pWl1, *pWh2, *pWl2, *pWh3, *pWl3;
    u16 *pNinh, *pNinl, *pXn1h, *pXn1l, *pWn1h, *pWn1l, *pWn2h, *pWn2l;
    cudaGetSymbolAddress((void**)&pW1s,   gW1s);
    cudaGetSymbolAddress((void**)&pNself, gNself);
    cudaGetSymbolAddress((void**)&pYself, gYself);
    cudaGetSymbolAddress((void**)&pw,     g_w);
    cudaGetSymbolAddress((void**)&pdsq,   g_dsq);
    cudaGetSymbolAddress((void**)&pB2h, gB2h);  cudaGetSymbolAddress((void**)&pB2l, gB2l);
    cudaGetSymbolAddress((void**)&pC3h, gC3h);  cudaGetSymbolAddress((void**)&pC3l, gC3l);
    cudaGetSymbolAddress((void**)&pWh1, gWh1);  cudaGetSymbolAddress((void**)&pWl1, gWl1);
    cudaGetSymbolAddress((void**)&pWh2, gWh2);  cudaGetSymbolAddress((void**)&pWl2, gWl2);
    cudaGetSymbolAddress((void**)&pWh3, gWh3);  cudaGetSymbolAddress((void**)&pWl3, gWl3);
    cudaGetSymbolAddress((void**)&pNinh, gNinh); cudaGetSymbolAddress((void**)&pNinl, gNinl);
    cudaGetSymbolAddress((void**)&pXn1h, gXn1h); cudaGetSymbolAddress((void**)&pXn1l, gXn1l);
    cudaGetSymbolAddress((void**)&pWn1h, gWn1h); cudaGetSymbolAddress((void**)&pWn1l, gWn1l);
    cudaGetSymbolAddress((void**)&pWn2h, gWn2h); cudaGetSymbolAddress((void**)&pWn2l, gWn2l);

    const int SM4  = (4 * 2048 + 4096 + 256) * 4;
    const int SMM1 = 4 * 128 * (64 + 8) * 2;    // 73728
    const int SMM2 = 4 * 128 * (128 + 8) * 2;   // 139264
    const int SMN1 = 4 * 128 * (192 + 8) * 2;   // 204800
    cudaFuncSetAttribute(gemm_stage<4, 1>,  cudaFuncAttributeMaxDynamicSharedMemorySize, SM4);
    cudaFuncSetAttribute(mma_stage1,        cudaFuncAttributeMaxDynamicSharedMemorySize, SMM1);
    cudaFuncSetAttribute(mma_stage<128, 2>, cudaFuncAttributeMaxDynamicSharedMemorySize, SMM2);
    cudaFuncSetAttribute(mma_stage<128, 3>, cudaFuncAttributeMaxDynamicSharedMemorySize, SMM2);
    cudaFuncSetAttribute(mma_stage<192, 0>, cudaFuncAttributeMaxDynamicSharedMemorySize, SMN1);
    cudaFuncSetAttribute(mma_stage<128, 5>, cudaFuncAttributeMaxDynamicSharedMemorySize, SMM2);

    // launch order: knn is the 4th kernel launch (ncu capture lands on #4)
    prep_kernel<<<(N + 255) / 256, 256>>>(coords, N);
    prep_weights_edge<<<192, 256>>>(We1, We2, Wc1);
    prep_weights_node<<<160, 256>>>(Wn1, Wn2);
    knn_kernel<<<(N + KNN_WARPS - 1) / KNN_WARPS, 256>>>(rs, nrs, N, out_nidx, out_d);
    build_ns<<<(N * 16 + 255) / 256, 256>>>(h, N);

    // Yself = h_self @ We1[1:65] + be1   (pre-activation partial, fp32)
    gemm_stage<4, 1><<<ntiles, 256, SM4>>>(pNself, 64, pW1s, be1, pYself, 128, N);

    // edge MLP on HMMA (bf16 hi/lo split); stage 1 gathers h_neig in-kernel
    mma_stage1<<<tiles, 256, SMM1>>>(h, pWh1, pWl1, We1, pYself, pdsq, pB2h, pB2l);
    mma_stage<128, 2><<<tiles, 256, SMM2>>>(pB2h, pB2l, pWh2, pWl2,
                                            be2, nullptr, nullptr,
                                            pC3h, pC3l, pNinh, pNinl,
                                            nullptr, nullptr, 0);
    mma_stage<128, 3><<<tiles, 256, SMM2>>>(pC3h, pC3l, pWh3, pWl3,
                                            bc1, Wc2, bc2,
                                            nullptr, nullptr, nullptr, nullptr,
                                            pw, nullptr, 0);

    coords_kernel<<<(N + 255) / 256, 256>>>(coords, coords_out, N);

    // node MLP on HMMA
    mma_stage<192, 0><<<ntiles, 256, SMN1>>>(pNinh, pNinl, pWn1h, pWn1l,
                                             bn1, nullptr, nullptr,
                                             pXn1h, pXn1l, nullptr, nullptr,
                                             nullptr, nullptr, 0);
    mma_stage<128, 5><<<ntiles, 256, SMM2>>>(pXn1h, pXn1l, pWn2h, pWn2l,
                                             bn2, nullptr, nullptr,
                                             nullptr, nullptr, nullptr, nullptr,
                                             nullptr, out, N);
}

// round 16
// speedup vs baseline: 1.0175x; 1.0175x over previous
#include <cuda_runtime.h>
#include <cstdint>

#define MAXN 10000
#define KNBR 16
#define MAXE (MAXN * KNBR)
#define FDIM 64
#define HDIM 128

typedef unsigned long long u64;
typedef unsigned int u32;
typedef unsigned short u16;

// ---------------- scratch (no allocations allowed) ----------------
__device__ int   g_nidx[MAXE];
__device__ float g_dsq [MAXE];
__device__ int   g_selfi[MAXN];
__device__ float g_w[MAXE];
__device__ __align__(16) float g_sx[MAXN];
__device__ __align__(16) float g_sy[MAXN];
__device__ __align__(16) float g_sz[MAXN];
__device__ __align__(16) float g_sn[MAXN];
__device__ __align__(16) float gW1s[64 * 128];
__device__ __align__(16) float gNself[(size_t)(MAXN + 128) * 64];
__device__ __align__(16) float gYself[(size_t)(MAXN + 128) * 128];
// bf16 hi/lo operand images, plain row-major
__device__ __align__(16) u16 gB2h[(size_t)MAXE * 128];
__device__ __align__(16) u16 gB2l[(size_t)MAXE * 128];
__device__ __align__(16) u16 gC3h[(size_t)MAXE * 128];
__device__ __align__(16) u16 gC3l[(size_t)MAXE * 128];
// node-path images
__device__ __align__(16) u16 gNinh[(size_t)(MAXN + 128) * 192];
__device__ __align__(16) u16 gNinl[(size_t)(MAXN + 128) * 192];
__device__ __align__(16) u16 gXn1h[(size_t)(MAXN + 128) * 128];
__device__ __align__(16) u16 gXn1l[(size_t)(MAXN + 128) * 128];
// weight images, transposed: Wt[n][k]
__device__ __align__(16) u16 gWh1[128 * 64],  gWl1[128 * 64];
__device__ __align__(16) u16 gWh2[128 * 128], gWl2[128 * 128];
__device__ __align__(16) u16 gWh3[128 * 128], gWl3[128 * 128];
__device__ __align__(16) u16 gWn1h[128 * 192], gWn1l[128 * 192];
__device__ __align__(16) u16 gWn2h[128 * 128], gWn2l[128 * 128];

// ---------------- generic helpers ----------------
__device__ __forceinline__ u64 pk2(float lo, float hi) {
    u64 r; asm("mov.b64 %0, {%1, %2};" : "=l"(r) : "f"(lo), "f"(hi)); return r;
}
__device__ __forceinline__ void upk2(u64 v, float& lo, float& hi) {
    asm("mov.b64 {%0, %1}, %2;" : "=f"(lo), "=f"(hi) : "l"(v));
}
__device__ __forceinline__ void fma2(u64& d, u64 a, u64 b) {
    asm("fma.rn.f32x2 %0, %1, %2, %0;" : "+l"(d) : "l"(a), "l"(b));
}
__device__ __forceinline__ u64 mk_key(float d, int j) {
    u64 k; asm("mov.b64 %0, {%1, %2};" : "=l"(k) : "r"(j), "r"(__float_as_uint(d)));
    return k;
}
__device__ __forceinline__ float selu_f(float x) {
    const float sc = 1.0507009873554805f;
    const float sa = 1.7580993408473766f;  // sc * alpha
    float e   = __expf(x);
    float neg = __fmaf_rn(sa, e, -sa);
    return x > 0.f ? sc * x : neg;
}
__device__ __forceinline__ void cpa16(u32 dst, const void* src) {
    asm volatile("cp.async.cg.shared.global [%0], [%1], 16;" :: "r"(dst), "l"(src));
}
__device__ __forceinline__ u32 smem_u32(const void* p) {
    u32 a; asm("{ .reg .u64 t; cvta.to.shared.u64 t, %1; cvt.u32.u64 %0, t; }" : "=r"(a) : "l"(p));
    return a;
}
// pack two f32 -> bf16x2 (low half = x0, high half = x1)
__device__ __forceinline__ u32 pack2bf(float x0, float x1) {
    u32 r; asm("cvt.rn.bf16x2.f32 %0, %1, %2;" : "=r"(r) : "f"(x1), "f"(x0)); return r;
}
// bf16 mma m16n8k16, f32 accumulate
__device__ __forceinline__ void hmma(float (&d)[4], u32 a0, u32 a1, u32 a2, u32 a3,
                                     u32 b0, u32 b1) {
    asm volatile(
        "mma.sync.aligned.m16n8k16.row.col.f32.bf16.bf16.f32 "
        "{%0,%1,%2,%3}, {%4,%5,%6,%7}, {%8,%9}, {%0,%1,%2,%3};"
        : "+f"(d[0]), "+f"(d[1]), "+f"(d[2]), "+f"(d[3])
        : "r"(a0), "r"(a1), "r"(a2), "r"(a3), "r"(b0), "r"(b1));
}

// ---------------- prep: SoA coords + norms ----------------
__global__ void prep_kernel(const float* __restrict__ coords, int N) {
    int i = blockIdx.x * 256 + threadIdx.x;
    if (i < N) {
        float x = coords[3 * i + 0];
        float y = coords[3 * i + 1];
        float z = coords[3 * i + 2];
        g_sx[i] = x; g_sy[i] = y; g_sz[i] = z;
        g_sn[i] = __fmaf_rn(z, z, __fmaf_rn(y, y, __fmul_rn(x, x)));
    }
}

// ---------------- KNN: warp-distributed sorted top-17 (R13 structure,
// deferred clamp/key + peeled tail) ----------------
#define KNN_WARPS 8
#define KSENT 0x7F800000FFFFFFFFull   // +inf distance sentinel

__global__ void __launch_bounds__(256)
knn_kernel(const int* __restrict__ rs, int nrs, int N,
           float* __restrict__ out_nidx_f, float* __restrict__ out_d)
{
    const int w    = threadIdx.x >> 5;
    const int lane = threadIdx.x & 31;
    const int row  = blockIdx.x * KNN_WARPS + w;
    (void)w;
    if (row >= N) return;

    int s0 = 0, s1 = N;
    for (int s = 0; s + 1 < nrs; ++s) {
        int a_ = rs[s], b_ = rs[s + 1];
        if (a_ <= row && row < b_) { s0 = a_; s1 = b_; }
    }

    const float xi = g_sx[row], yi = g_sy[row], zi = g_sz[row], ni = g_sn[row];

    u64 L    = KSENT;                           // warp-distributed list entry
    u64 curT = KSENT;                           // current 17th-smallest (L[16])
    float Tf = __uint_as_float(0x7F800000u);    // +inf (always >= 0)

    auto insert_key = [&](u64 k) {
        unsigned bal = __ballot_sync(0xffffffffu, L <= k);
        int pos = __popc(bal);                  // <= 16 since k < L[16]
        u64 up = __shfl_up_sync(0xffffffffu, L, 1);
        if (lane == pos)                 L = k;
        else if (lane > pos && lane < 17) L = up;
        curT = __shfl_sync(0xffffffffu, L, 16);
        Tf = __uint_as_float((u32)(curT >> 32));
    };

    // commit with deferred clamp+key: d2u is UNCLAMPED; pass test d2u<=Tf is
    // exactly equivalent to max(d2u,0)<=Tf since Tf >= 0 always.
    auto commitdj = [&](float d2u, int j, bool pass) {
        unsigned pb = __ballot_sync(0xffffffffu, pass);
        while (pb) {
            int src = __ffs(pb) - 1; pb &= pb - 1;
            float dd = __shfl_sync(0xffffffffu, d2u, src);
            int   jj = __shfl_sync(0xffffffffu, j,   src);
            u64 k = mk_key(fmaxf(dd, 0.f), jj);  // exact clamped key
            if (k < curT) insert_key(k);         // warp-uniform branch
        }
    };

    auto d2u_of = [&](float xj, float yj, float zj, float nj) {
        float dot = __fmul_rn(xi, xj);
        dot = __fmaf_rn(yi, yj, dot);
        dot = __fmaf_rn(zi, zj, dot);
        float nn = __fadd_rn(ni, nj);
        return __fmaf_rn(-2.f, dot, nn);         // unclamped
    };

    // ---- prolog: align to 4 ----
    int jb = (s0 + 3) & ~3;
    if (jb > s1) jb = s1;
    {
        int pre = jb - s0;                      // 0..3
        bool act = lane < pre;
        int j = s0 + (act ? lane : 0);
        float d2 = d2u_of(g_sx[j], g_sy[j], g_sz[j], g_sn[j]);
        commitdj(d2, j, act && d2 <= Tf);
    }

    const int nquad = (s1 - jb) >> 2;
    const int rem   = (s1 - jb) & 3;

    // ---- main quad loop: all lanes fully active (tail peeled) ----
    int q0 = 0;
    for (; q0 + 32 <= nquad; q0 += 32) {
        int j = jb + 4 * (q0 + lane);
        float4 X  = *(const float4*)(g_sx + j);
        float4 Y  = *(const float4*)(g_sy + j);
        float4 Z  = *(const float4*)(g_sz + j);
        float4 Nn = *(const float4*)(g_sn + j);
        float d0  = d2u_of(X.x, Y.x, Z.x, Nn.x);
        float d1  = d2u_of(X.y, Y.y, Z.y, Nn.y);
        float d2v = d2u_of(X.z, Y.z, Z.z, Nn.z);
        float d3  = d2u_of(X.w, Y.w, Z.w, Nn.w);
        commitdj(d0,  j,     d0  <= Tf);
        commitdj(d1,  j + 1, d1  <= Tf);
        commitdj(d2v, j + 2, d2v <= Tf);
        commitdj(d3,  j + 3, d3  <= Tf);
    }

    // ---- peeled tail iteration (partially active) ----
    if (q0 < nquad) {
        bool act = (q0 + lane) < nquad;
        int j = jb + 4 * (act ? (q0 + lane) : 0);
        float4 X  = *(const float4*)(g_sx + j);
        float4 Y  = *(const float4*)(g_sy + j);
        float4 Z  = *(const float4*)(g_sz + j);
        float4 Nn = *(const float4*)(g_sn + j);
        float d0  = d2u_of(X.x, Y.x, Z.x, Nn.x);
        float d1  = d2u_of(X.y, Y.y, Z.y, Nn.y);
        float d2v = d2u_of(X.z, Y.z, Z.z, Nn.z);
        float d3  = d2u_of(X.w, Y.w, Z.w, Nn.w);
        commitdj(d0,  j,     act && d0  <= Tf);
        commitdj(d1,  j + 1, act && d1  <= Tf);
        commitdj(d2v, j + 2, act && d2v <= Tf);
        commitdj(d3,  j + 3, act && d3  <= Tf);
    }

    // ---- remainder ----
    if (rem) {
        bool act = lane < rem;
        int j = jb + 4 * nquad + (act ? lane : 0);
        float d2 = d2u_of(g_sx[j], g_sy[j], g_sz[j], g_sn[j]);
        commitdj(d2, j, act && d2 <= Tf);
    }

    // ---- emit: lanes 0..16 hold the sorted top-17 ----
    if (lane < 17) {
        u32 jj = (u32)(L & 0xffffffffu);
        float dd = __uint_as_float((u32)(L >> 32));
        if (lane == 0) {
            g_selfi[row] = (int)jj;
        } else {
            int t = lane - 1;
            g_nidx[row * KNBR + t] = (int)jj;
            g_dsq [row * KNBR + t] = dd;
            out_nidx_f[row * KNBR + t] = (float)(int)jj;
            out_d    [row * KNBR + t] = dd;
        }
    }
}

// ---------------- weight / image prep (merged) ----------------
__device__ __forceinline__ void wimg_body(const float* __restrict__ W, int K, int roff,
                                          u16* __restrict__ hi, u16* __restrict__ lo,
                                          int idx) {
    if (idx < K * 128) {
        int n = idx / K, k = idx - n * K;
        float v = W[(roff + k) * 128 + n];
        u32 ph = pack2bf(v, 0.f);
        float vh = __uint_as_float(ph << 16);
        u32 pl = pack2bf(v - vh, 0.f);
        hi[idx] = (u16)(ph & 0xffffu);
        lo[idx] = (u16)(pl & 0xffffu);
    }
}

// blocks [0,32): gW1s; [32,64): We1 img; [64,128): We2 img; [128,192): Wc1 img
__global__ void prep_weights_edge(const float* __restrict__ We1,
                                  const float* __restrict__ We2,
                                  const float* __restrict__ Wc1) {
    int b = blockIdx.x, tid = threadIdx.x;
    if (b < 32) {
        int i = b * 256 + tid;
        int k = i >> 7, n = i & 127;
        gW1s[i] = We1[(1 + k) * 128 + n];
    } else if (b < 64) {
        wimg_body(We1, 64, 65, gWh1, gWl1, (b - 32) * 256 + tid);
    } else if (b < 128) {
        wimg_body(We2, 128, 0, gWh2, gWl2, (b - 64) * 256 + tid);
    } else {
        wimg_body(Wc1, 128, 0, gWh3, gWl3, (b - 128) * 256 + tid);
    }
}

// blocks [0,96): Wn1 img (K=192); [96,160): Wn2 img
__global__ void prep_weights_node(const float* __restrict__ Wn1,
                                  const float* __restrict__ Wn2) {
    int b = blockIdx.x, tid = threadIdx.x;
    if (b < 96) wimg_body(Wn1, 192, 0, gWn1h, gWn1l, b * 256 + tid);
    else        wimg_body(Wn2, 128, 0, gWn2h, gWn2l, (b - 96) * 256 + tid);
}

// gNself[n] = h[self(n)] fp32 (for Yself stage); node-input image cols 128:192 = h_self hi/lo
__global__ void build_ns(const float* __restrict__ h, int N) {
    int idx = blockIdx.x * 256 + threadIdx.x;
    if (idx < N * 16) {
        int n = idx >> 4, q = idx & 15;
        float4 v = *(const float4*)(h + (size_t)g_selfi[n] * FDIM + q * 4);
        *(float4*)(gNself + (size_t)n * 64 + q * 4) = v;
        u32 ph0 = pack2bf(v.x, v.y);
        u32 ph1 = pack2bf(v.z, v.w);
        float a0 = __uint_as_float(ph0 << 16), a1 = __uint_as_float(ph0 & 0xffff0000u);
        float a2 = __uint_as_float(ph1 << 16), a3 = __uint_as_float(ph1 & 0xffff0000u);
        u32 pl0 = pack2bf(v.x - a0, v.y - a1);
        u32 pl1 = pack2bf(v.z - a2, v.w - a3);
        size_t off = (size_t)n * 192 + 128 + q * 4;
        *(u32*)(gNinh + off)     = ph0;  *(u32*)(gNinh + off + 2) = ph1;
        *(u32*)(gNinl + off)     = pl0;  *(u32*)(gNinl + off + 2) = pl1;
    }
}

// coords_new = coords + mean_k((c_i - c_j) * w)
__global__ void coords_kernel(const float* __restrict__ coords,
                              float* __restrict__ cout, int N) {
    int n = blockIdx.x * 256 + threadIdx.x;
    if (n < N) {
        float cx = coords[n * 3 + 0];
        float cy = coords[n * 3 + 1];
        float cz = coords[n * 3 + 2];
        float sx = 0.f, sy = 0.f, sz = 0.f;
#pragma unroll
        for (int k = 0; k < 16; ++k) {
            int j = g_nidx[n * 16 + k];
            float wv = g_w[n * 16 + k];
            sx += (cx - coords[j * 3 + 0]) * wv;
            sy += (cy - coords[j * 3 + 1]) * wv;
            sz += (cz - coords[j * 3 + 2]) * wv;
        }
        cout[n * 3 + 0] = cx + sx * 0.0625f;
        cout[n * 3 + 1] = cy + sy * 0.0625f;
        cout[n * 3 + 2] = cz + sz * 0.0625f;
    }
}

// ---------------- R5 FFMA staged GEMM (Yself; proven) ----------------
__device__ __forceinline__ void mma_chunk8(const float* __restrict__ As,
                                           const float* __restrict__ Ws,
                                           u64 (&acc)[8][4], int m0, int n0)
{
#pragma unroll
    for (int s = 0; s < 4; ++s) {
        float4 av[8];
#pragma unroll
        for (int i = 0; i < 8; ++i)
            av[i] = *(const float4*)(As + (m0 + i) * 16 + s * 4);
#pragma unroll
        for (int r = 0; r < 4; ++r) {
            const float* wr = Ws + (s * 4 + r) * 128 + n0;
            ulonglong2 b0 = *(const ulonglong2*)wr;
            ulonglong2 b1 = *(const ulonglong2*)(wr + 4);
#pragma unroll
            for (int i = 0; i < 8; ++i) {
                float a_ = (r == 0) ? av[i].x : (r == 1) ? av[i].y : (r == 2) ? av[i].z : av[i].w;
                u64 aa = pk2(a_, a_);
                fma2(acc[i][0], aa, b0.x);
                fma2(acc[i][1], aa, b0.y);
                fma2(acc[i][2], aa, b1.x);
                fma2(acc[i][3], aa, b1.y);
            }
        }
    }
}

template<int KCH, int EPI>   // EPI: 0 = selu+store, 1 = store
__global__ void __launch_bounds__(256, 2)
gemm_stage(const float* __restrict__ A, int lda,
           const float* __restrict__ Wg, const float* __restrict__ bias,
           float* __restrict__ O, int ldo, int M)
{
    extern __shared__ float sm[];
    float* Ws = sm;
    float* As = Ws + KCH * 2048;
    float* sb = As + 4096;

    const int tid = threadIdx.x;
    const int tx = tid & 15, ty = tid >> 4;
    const int n0 = tx * 8,   m0 = ty * 8;
    const long row0 = (long)blockIdx.x * 128;

    for (int i = tid; i < KCH * 512; i += 256)
        ((float4*)Ws)[i] = ((const float4*)Wg)[i];
    if (tid < 32) ((float4*)sb)[tid] = ((const float4*)bias)[tid];

    const u32 asu = (u32)__cvta_generic_to_shared(As);
    auto issue = [&](int c, int bufsel) {
        const float* srcbase = A + row0 * lda + c * 16;
        u32 d0 = asu + (u32)(bufsel * 2048 * 4);
        int q = tid;   int r = q >> 2, kq = q & 3;
        cpa16(d0 + (u32)((r * 16 + kq * 4) * 4), srcbase + (long)r * lda + kq * 4);
        q = tid + 256; r = q >> 2; kq = q & 3;
        cpa16(d0 + (u32)((r * 16 + kq * 4) * 4), srcbase + (long)r * lda + kq * 4);
        asm volatile("cp.async.commit_group;");
    };

    issue(0, 0);
    __syncthreads();

    u64 acc[8][4];
#pragma unroll
    for (int i = 0; i < 8; ++i)
#pragma unroll
        for (int j = 0; j < 4; ++j)
            acc[i][j] = pk2(sb[n0 + 2 * j], sb[n0 + 2 * j + 1]);

#pragma unroll 1
    for (int c = 0; c < KCH; ++c) {
        if (c + 1 < KCH) {
            issue(c + 1, (c + 1) & 1);
            asm volatile("cp.async.wait_group 1;");
        } else {
            asm volatile("cp.async.wait_group 0;");
        }
        __syncthreads();
        mma_chunk8(As + (c & 1) * 2048, Ws + c * 2048, acc, m0, n0);
        __syncthreads();
    }

#pragma unroll
    for (int i = 0; i < 8; ++i) {
        long grow = row0 + m0 + i;
        if (grow < M) {
            float o[8];
#pragma unroll
            for (int j = 0; j < 4; ++j) upk2(acc[i][j], o[2 * j], o[2 * j + 1]);
            if (EPI == 0) {
#pragma unroll
                for (int j = 0; j < 8; ++j) o[j] = selu_f(o[j]);
            }
            *(float4*)(O + grow * ldo + n0)     = make_float4(o[0], o[1], o[2], o[3]);
            *(float4*)(O + grow * ldo + n0 + 4) = make_float4(o[4], o[5], o[6], o[7]);
        }
    }
}

// ---------------- fused edge stage 1: gather h_neig + HMMA (KK=64) ----------
__global__ void __launch_bounds__(256)
mma_stage1(const float* __restrict__ h,
           const u16* __restrict__ Wih, const u16* __restrict__ Wil,
           const float* __restrict__ aux,     // We1 row 0
           const float* __restrict__ yselfg,
           const float* __restrict__ dsqg,
           u16* __restrict__ outHi, u16* __restrict__ outLo)
{
    constexpr int KK = 64;
    constexpr int SA = KK + 8;
    extern __shared__ u16 smu[];
    u16* sAh = smu;
    u16* sAl = sAh + 128 * SA;
    u16* sWh = sAl + 128 * SA;
    u16* sWl = sWh + 128 * SA;

    const int tid  = threadIdx.x;
    const int w    = tid >> 5;
    const int lane = tid & 31;
    const int g    = lane >> 2;
    const int tig  = lane & 3;
    const int tile = blockIdx.x;

    // ---- W copies via cp.async (overlap with A gather) ----
    const u32 sb = smem_u32(smu);
    for (int i = tid; i < 1024; i += 256) {        // 128 rows x 8 chunks
        int r = i >> 3, c = i & 7;
        u32 dof = (u32)((r * SA + c * 8) * 2);
        u32 sof = (u32)((r * KK + c * 8) * 2);
        cpa16(sb + 2 * 128 * SA * 2 + dof, (const char*)Wih + sof);
        cpa16(sb + 3 * 128 * SA * 2 + dof, (const char*)Wil + sof);
    }
    asm volatile("cp.async.commit_group;");

    // ---- A gather: 2 threads per row, 32 floats each ----
    {
        int r  = tid >> 1;
        int hf = tid & 1;
        int nb = g_nidx[tile * 128 + r];
        const float* hr = h + (size_t)nb * FDIM + hf * 32;
        u16* dh = sAh + r * SA + hf * 32;
        u16* dl = sAl + r * SA + hf * 32;
#pragma unroll
        for (int c = 0; c < 4; ++c) {
            float4 f0 = *(const float4*)(hr + c * 8);
            float4 f1 = *(const float4*)(hr + c * 8 + 4);
            float x[8] = {f0.x, f0.y, f0.z, f0.w, f1.x, f1.y, f1.z, f1.w};
            u32 hp[4], lp[4];
#pragma unroll
            for (int q = 0; q < 4; ++q) {
                u32 ph = pack2bf(x[2 * q], x[2 * q + 1]);
                float h0 = __uint_as_float(ph << 16);
                float h1 = __uint_as_float(ph & 0xffff0000u);
                hp[q] = ph;
                lp[q] = pack2bf(x[2 * q] - h0, x[2 * q + 1] - h1);
            }
            *(uint4*)(dh + c * 8) = make_uint4(hp[0], hp[1], hp[2], hp[3]);
            *(uint4*)(dl + c * 8) = make_uint4(lp[0], lp[1], lp[2], lp[3]);
        }
    }

    // ---- accumulator init (zero; bias folded via Yself) ----
    float acc[16][4];
#pragma unroll
    for (int nt = 0; nt < 16; ++nt) {
        acc[nt][0] = 0.f; acc[nt][1] = 0.f; acc[nt][2] = 0.f; acc[nt][3] = 0.f;
    }

    asm volatile("cp.async.wait_group 0;");
    __syncthreads();

    const int rA0 = (16 * w + g) * SA;
    const int rA1 = (16 * w + g + 8) * SA;

#pragma unroll
    for (int k0 = 0; k0 < KK; k0 += 16) {
        const int co = k0 + 2 * tig;
        u32 ah0 = *(const u32*)(sAh + rA0 + co);
        u32 ah1 = *(const u32*)(sAh + rA1 + co);
        u32 ah2 = *(const u32*)(sAh + rA0 + co + 8);
        u32 ah3 = *(const u32*)(sAh + rA1 + co + 8);
        u32 al0 = *(const u32*)(sAl + rA0 + co);
        u32 al1 = *(const u32*)(sAl + rA1 + co);
        u32 al2 = *(const u32*)(sAl + rA0 + co + 8);
        u32 al3 = *(const u32*)(sAl + rA1 + co + 8);
#pragma unroll
        for (int nt = 0; nt < 16; ++nt) {
            const int rb = (nt * 8 + g) * SA + co;
            u32 bh0 = *(const u32*)(sWh + rb);
            u32 bh1 = *(const u32*)(sWh + rb + 8);
            u32 bl0 = *(const u32*)(sWl + rb);
            u32 bl1 = *(const u32*)(sWl + rb + 8);
            hmma(acc[nt], ah0, ah1, ah2, ah3, bh0, bh1);
            hmma(acc[nt], ah0, ah1, ah2, ah3, bl0, bl1);
            hmma(acc[nt], al0, al1, al2, al3, bh0, bh1);
        }
    }

    // ---- epilogue (EPI1) ----
    const int node = tile * 8 + w;
    float dsq_r[2];
    dsq_r[0] = dsqg[(size_t)tile * 128 + 16 * w + g];
    dsq_r[1] = dsqg[(size_t)tile * 128 + 16 * w + g + 8];

#pragma unroll
    for (int nt = 0; nt < 16; ++nt) {
        const int col = nt * 8 + 2 * tig;
        float2 t = *(const float2*)(yselfg + (size_t)node * 128 + col);
        float2 u = *(const float2*)(aux + col);
#pragma unroll
        for (int r = 0; r < 2; ++r) {
            const int row = 16 * w + g + 8 * r;
            const size_t gr = (size_t)tile * 128 + row;
            float v0 = acc[nt][2 * r]     + t.x + dsq_r[r] * u.x;
            float v1 = acc[nt][2 * r + 1] + t.y + dsq_r[r] * u.y;
            v0 = selu_f(v0); v1 = selu_f(v1);
            u32 ph = pack2bf(v0, v1);
            float h0 = __uint_as_float(ph << 16);
            float h1 = __uint_as_float(ph & 0xffff0000u);
            u32 pl = pack2bf(v0 - h0, v1 - h1);
            *(u32*)((char*)outHi + (gr * 128 + col) * 2) = ph;
            *(u32*)((char*)outLo + (gr * 128 + col) * 2) = pl;
        }
    }
}

// ---------------- HMMA GEMM stage (bf16 hi/lo 3-term split) ----------------
// EPI: 0 = bias+selu, emit bf16 images                       (node stage 1)
//      2 = bias+selu, emit bf16 images, e_sum -> esum images (edge stage 2)
//      3 = bias+selu, dot with Wc2 -> g_w                    (edge stage 3)
//      5 = bias, fp32 store (bounds-checked)                 (node stage 2)
template<int KK, int EPI>
__global__ void __launch_bounds__(256)
mma_stage(const u16* __restrict__ Aih, const u16* __restrict__ Ail,
          const u16* __restrict__ Wih, const u16* __restrict__ Wil,
          const float* __restrict__ biasg,
          const float* __restrict__ aux,     // EPI3: Wc2
          const float* __restrict__ bc2g,    // EPI3
          u16* __restrict__ outHi, u16* __restrict__ outLo,   // EPI 0/2
          u16* __restrict__ esumHi, u16* __restrict__ esumLo, // EPI2
          float* __restrict__ woutg,         // EPI3
          float* __restrict__ Og, int M)     // EPI5
{
    constexpr int SA = KK + 8;
    extern __shared__ u16 smu[];
    u16* sAh = smu;
    u16* sAl = sAh + 128 * SA;
    u16* sWh = sAl + 128 * SA;
    u16* sWl = sWh + 128 * SA;

    const int tid  = threadIdx.x;
    const int w    = tid >> 5;
    const int lane = tid & 31;
    const int g    = lane >> 2;
    const int tig  = lane & 3;
    const int tile = blockIdx.x;

    // ---- async copies: two commit groups, split by K-halves ----
    constexpr int CPR = KK / 8;
    constexpr int HC  = CPR / 2;
    const u32 sb = smem_u32(smu);
    {
        const char* sa = (const char*)Aih + (size_t)tile * 128 * KK * 2;
        const char* sl = (const char*)Ail + (size_t)tile * 128 * KK * 2;
#pragma unroll
        for (int hh = 0; hh < 2; ++hh) {
            for (int i = tid; i < 128 * HC; i += 256) {
                int r = i / HC, c = hh * HC + (i - (i / HC) * HC);
                u32 dof = (u32)((r * SA + c * 8) * 2);
                u32 sof = (u32)((r * KK + c * 8) * 2);
                cpa16(sb + dof,                   sa + sof);
                cpa16(sb + 128 * SA * 2 + dof,    sl + sof);
                cpa16(sb + 2 * 128 * SA * 2 + dof, (const char*)Wih + sof);
                cpa16(sb + 3 * 128 * SA * 2 + dof, (const char*)Wil + sof);
            }
            asm volatile("cp.async.commit_group;");
        }
    }

    // ---- accumulator init (bias) ----
    float acc[16][4];
#pragma unroll
    for (int nt = 0; nt < 16; ++nt) {
        float b0 = __ldg(biasg + nt * 8 + 2 * tig);
        float b1 = __ldg(biasg + nt * 8 + 2 * tig + 1);
        acc[nt][0] = b0; acc[nt][1] = b1; acc[nt][2] = b0; acc[nt][3] = b1;
    }

    const int rA0 = (16 * w + g) * SA;
    const int rA1 = (16 * w + g + 8) * SA;

    auto mma_k = [&](int k0) {
        const int co = k0 + 2 * tig;
        u32 ah0 = *(const u32*)(sAh + rA0 + co);
        u32 ah1 = *(const u32*)(sAh + rA1 + co);
        u32 ah2 = *(const u32*)(sAh + rA0 + co + 8);
        u32 ah3 = *(const u32*)(sAh + rA1 + co + 8);
        u32 al0 = *(const u32*)(sAl + rA0 + co);
        u32 al1 = *(const u32*)(sAl + rA1 + co);
        u32 al2 = *(const u32*)(sAl + rA0 + co + 8);
        u32 al3 = *(const u32*)(sAl + rA1 + co + 8);
#pragma unroll
        for (int nt = 0; nt < 16; ++nt) {
            const int rb = (nt * 8 + g) * SA + co;
            u32 bh0 = *(const u32*)(sWh + rb);
            u32 bh1 = *(const u32*)(sWh + rb + 8);
            u32 bl0 = *(const u32*)(sWl + rb);
            u32 bl1 = *(const u32*)(sWl + rb + 8);
            hmma(acc[nt], ah0, ah1, ah2, ah3, bh0, bh1);
            hmma(acc[nt], ah0, ah1, ah2, ah3, bl0, bl1);
            hmma(acc[nt], al0, al1, al2, al3, bh0, bh1);
        }
    };

    asm volatile("cp.async.wait_group 1;");
    __syncthreads();
#pragma unroll
    for (int k0 = 0; k0 < KK / 2; k0 += 16) mma_k(k0);

    asm volatile("cp.async.wait_group 0;");
    __syncthreads();
#pragma unroll
    for (int k0 = KK / 2; k0 < KK; k0 += 16) mma_k(k0);

    // ---- epilogue ----
    const int node = tile * 8 + w;
    float pr[2] = {0.f, 0.f};

#pragma unroll
    for (int nt = 0; nt < 16; ++nt) {
        const int col = nt * 8 + 2 * tig;
        float wv0 = 0.f, wv1 = 0.f;
        if (EPI == 3) {
            float2 u = *(const float2*)(aux + col);
            wv0 = u.x; wv1 = u.y;
        }
        float ps0 = 0.f, ps1 = 0.f;
#pragma unroll
        for (int r = 0; r < 2; ++r) {
            const int row = 16 * w + g + 8 * r;
            const size_t gr = (size_t)tile * 128 + row;
            float v0 = acc[nt][2 * r];
            float v1 = acc[nt][2 * r + 1];
            if (EPI != 5) { v0 = selu_f(v0); v1 = selu_f(v1); }
            if (EPI == 0 || EPI == 2) {
                u32 ph = pack2bf(v0, v1);
                float h0 = __uint_as_float(ph << 16);
                float h1 = __uint_as_float(ph & 0xffff0000u);
                u32 pl = pack2bf(v0 - h0, v1 - h1);
                *(u32*)((char*)outHi + (gr * 128 + col) * 2) = ph;
                *(u32*)((char*)outLo + (gr * 128 + col) * 2) = pl;
            }
            if (EPI == 2) { ps0 += v0; ps1 += v1; }
            if (EPI == 3) { pr[r] = fmaf(v0, wv0, fmaf(v1, wv1, pr[r])); }
            if (EPI == 5) {
                if ((long)gr < M)
                    *(float2*)(Og + gr * 128 + col) = make_float2(v0, v1);
            }
        }
        if (EPI == 2) {
            ps0 += __shfl_xor_sync(0xffffffffu, ps0, 4);
            ps0 += __shfl_xor_sync(0xffffffffu, ps0, 8);
            ps0 += __shfl_xor_sync(0xffffffffu, ps0, 16);
            ps1 += __shfl_xor_sync(0xffffffffu, ps1, 4);
            ps1 += __shfl_xor_sync(0xffffffffu, ps1, 8);
            ps1 += __shfl_xor_sync(0xffffffffu, ps1, 16);
            if (g == 0) {
                u32 ph = pack2bf(ps0, ps1);
                float h0 = __uint_as_float(ph << 16);
                float h1 = __uint_as_float(ph & 0xffff0000u);
                u32 pl = pack2bf(ps0 - h0, ps1 - h1);
                size_t off = ((size_t)node * 192 + col) * 2;
                *(u32*)((char*)esumHi + off) = ph;
                *(u32*)((char*)esumLo + off) = pl;
            }
        }
    }
    if (EPI == 3) {
        const float bc = bc2g[0];
#pragma unroll
        for (int r = 0; r < 2; ++r) {
            float p = pr[r];
            p += __shfl_xor_sync(0xffffffffu, p, 1);
            p += __shfl_xor_sync(0xffffffffu, p, 2);
            if (tig == 0)
                woutg[(size_t)tile * 128 + 16 * w + g + 8 * r] = p + bc;
        }
    }
}

// ---------------- launch ----------------
extern "C" void kernel_launch(void* const* d_in, const int* in_sizes, int n_in,
                              void* d_out, int out_size)
{
    const float* h      = (const float*)d_in[0];
    const float* coords = (const float*)d_in[1];
    const int*   rs     = (const int*)  d_in[2];
    const float* We1 = (const float*)d_in[3];
    const float* be1 = (const float*)d_in[4];
    const float* We2 = (const float*)d_in[5];
    const float* be2 = (const float*)d_in[6];
    const float* Wc1 = (const float*)d_in[7];
    const float* bc1 = (const float*)d_in[8];
    const float* Wc2 = (const float*)d_in[9];
    const float* bc2 = (const float*)d_in[10];
    const float* Wn1 = (const float*)d_in[11];
    const float* bn1 = (const float*)d_in[12];
    const float* Wn2 = (const float*)d_in[13];
    const float* bn2 = (const float*)d_in[14];

    const int N   = in_sizes[1] / 3;
    const int nrs = in_sizes[2];
    const int E   = N * KNBR;
    const int tiles  = E / 128;
    const int ntiles = (N + 127) / 128;

    float* out        = (float*)d_out;               // [N,128]
    float* coords_out = out + (size_t)N * HDIM;      // [N,3]
    float* out_nidx   = coords_out + (size_t)N * 3;  // [N,16]
    float* out_d      = out_nidx + (size_t)N * KNBR; // [N,16]

    float *pW1s, *pNself, *pYself, *pw, *pdsq;
    u16 *pB2h, *pB2l, *pC3h, *pC3l;
    u16 *pWh1, *pWl1, *pWh2, *pWl2, *pWh3, *pWl3;
    u16 *pNinh, *pNinl, *pXn1h, *pXn1l, *pWn1h, *pWn1l, *pWn2h, *pWn2l;
    cudaGetSymbolAddress((void**)&pW1s,   gW1s);
    cudaGetSymbolAddress((void**)&pNself, gNself);
    cudaGetSymbolAddress((void**)&pYself, gYself);
    cudaGetSymbolAddress((void**)&pw,     g_w);
    cudaGetSymbolAddress((void**)&pdsq,   g_dsq);
    cudaGetSymbolAddress((void**)&pB2h, gB2h);  cudaGetSymbolAddress((void**)&pB2l, gB2l);
    cudaGetSymbolAddress((void**)&pC3h, gC3h);  cudaGetSymbolAddress((void**)&pC3l, gC3l);
    cudaGetSymbolAddress((void**)&pWh1, gWh1);  cudaGetSymbolAddress((void**)&pWl1, gWl1);
    cudaGetSymbolAddress((void**)&pWh2, gWh2);  cudaGetSymbolAddress((void**)&pWl2, gWl2);
    cudaGetSymbolAddress((void**)&pWh3, gWh3);  cudaGetSymbolAddress((void**)&pWl3, gWl3);
    cudaGetSymbolAddress((void**)&pNinh, gNinh); cudaGetSymbolAddress((void**)&pNinl, gNinl);
    cudaGetSymbolAddress((void**)&pXn1h, gXn1h); cudaGetSymbolAddress((void**)&pXn1l, gXn1l);
    cudaGetSymbolAddress((void**)&pWn1h, gWn1h); cudaGetSymbolAddress((void**)&pWn1l, gWn1l);
    cudaGetSymbolAddress((void**)&pWn2h, gWn2h); cudaGetSymbolAddress((void**)&pWn2l, gWn2l);

    const int SM4  = (4 * 2048 + 4096 + 256) * 4;
    const int SMM1 = 4 * 128 * (64 + 8) * 2;    // 73728
    const int SMM2 = 4 * 128 * (128 + 8) * 2;   // 139264
    const int SMN1 = 4 * 128 * (192 + 8) * 2;   // 204800
    cudaFuncSetAttribute(gemm_stage<4, 1>,  cudaFuncAttributeMaxDynamicSharedMemorySize, SM4);
    cudaFuncSetAttribute(mma_stage1,        cudaFuncAttributeMaxDynamicSharedMemorySize, SMM1);
    cudaFuncSetAttribute(mma_stage<128, 2>, cudaFuncAttributeMaxDynamicSharedMemorySize, SMM2);
    cudaFuncSetAttribute(mma_stage<128, 3>, cudaFuncAttributeMaxDynamicSharedMemorySize, SMM2);
    cudaFuncSetAttribute(mma_stage<192, 0>, cudaFuncAttributeMaxDynamicSharedMemorySize, SMN1);
    cudaFuncSetAttribute(mma_stage<128, 5>, cudaFuncAttributeMaxDynamicSharedMemorySize, SMM2);

    // launch order: knn is the 4th kernel launch (ncu capture lands on #4)
    prep_kernel<<<(N + 255) / 256, 256>>>(coords, N);
    prep_weights_edge<<<192, 256>>>(We1, We2, Wc1);
    prep_weights_node<<<160, 256>>>(Wn1, Wn2);
    knn_kernel<<<(N + KNN_WARPS - 1) / KNN_WARPS, 256>>>(rs, nrs, N, out_nidx, out_d);
    build_ns<<<(N * 16 + 255) / 256, 256>>>(h, N);

    // Yself = h_self @ We1[1:65] + be1   (pre-activation partial, fp32)
    gemm_stage<4, 1><<<ntiles, 256, SM4>>>(pNself, 64, pW1s, be1, pYself, 128, N);

    // edge MLP on HMMA (bf16 hi/lo split); stage 1 gathers h_neig in-kernel
    mma_stage1<<<tiles, 256, SMM1>>>(h, pWh1, pWl1, We1, pYself, pdsq, pB2h, pB2l);
    mma_stage<128, 2><<<tiles, 256, SMM2>>>(pB2h, pB2l, pWh2, pWl2,
                                            be2, nullptr, nullptr,
                                            pC3h, pC3l, pNinh, pNinl,
                                            nullptr, nullptr, 0);
    mma_stage<128, 3><<<tiles, 256, SMM2>>>(pC3h, pC3l, pWh3, pWl3,
                                            bc1, Wc2, bc2,
                                            nullptr, nullptr, nullptr, nullptr,
                                            pw, nullptr, 0);

    coords_kernel<<<(N + 255) / 256, 256>>>(coords, coords_out, N);

    // node MLP on HMMA
    mma_stage<192, 0><<<ntiles, 256, SMN1>>>(pNinh, pNinl, pWn1h, pWn1l,
                                             bn1, nullptr, nullptr,
                                             pXn1h, pXn1l, nullptr, nullptr,
                                             nullptr, nullptr, 0);
    mma_stage<128, 5><<<ntiles, 256, SMM2>>>(pXn1h, pXn1l, pWn2h, pWn2l,
                                             bn2, nullptr, nullptr,
                                             nullptr, nullptr, nullptr, nullptr,
                                             nullptr, out, N);
}

// round 17
// speedup vs baseline: 1.0748x; 1.0563x over previous
#include <cuda_runtime.h>
#include <cstdint>

#define MAXN 10000
#define KNBR 16
#define MAXE (MAXN * KNBR)
#define FDIM 64
#define HDIM 128

typedef unsigned long long u64;
typedef unsigned int u32;
typedef unsigned short u16;

// ---------------- scratch (no allocations allowed) ----------------
__device__ int   g_nidx[MAXE];
__device__ float g_dsq [MAXE];
__device__ int   g_selfi[MAXN];
__device__ float g_w[MAXE];
__device__ __align__(16) float g_sx[MAXN];
__device__ __align__(16) float g_sy[MAXN];
__device__ __align__(16) float g_sz[MAXN];
__device__ __align__(16) float g_sn[MAXN];
__device__ __align__(16) float gW1s[64 * 128];
__device__ __align__(16) float gNself[(size_t)(MAXN + 128) * 64];
__device__ __align__(16) float gYself[(size_t)(MAXN + 128) * 128];
// bf16 hi/lo operand images, plain row-major
__device__ __align__(16) u16 gB2h[(size_t)MAXE * 128];
__device__ __align__(16) u16 gB2l[(size_t)MAXE * 128];
__device__ __align__(16) u16 gC3h[(size_t)MAXE * 128];
__device__ __align__(16) u16 gC3l[(size_t)MAXE * 128];
// node-path images
__device__ __align__(16) u16 gNinh[(size_t)(MAXN + 128) * 192];
__device__ __align__(16) u16 gNinl[(size_t)(MAXN + 128) * 192];
__device__ __align__(16) u16 gXn1h[(size_t)(MAXN + 128) * 128];
__device__ __align__(16) u16 gXn1l[(size_t)(MAXN + 128) * 128];
// weight images, transposed: Wt[n][k]
__device__ __align__(16) u16 gWh1[128 * 64],  gWl1[128 * 64];
__device__ __align__(16) u16 gWh2[128 * 128], gWl2[128 * 128];
__device__ __align__(16) u16 gWh3[128 * 128], gWl3[128 * 128];
__device__ __align__(16) u16 gWn1h[128 * 192], gWn1l[128 * 192];
__device__ __align__(16) u16 gWn2h[128 * 128], gWn2l[128 * 128];

// ---------------- generic helpers ----------------
__device__ __forceinline__ u64 pk2(float lo, float hi) {
    u64 r; asm("mov.b64 %0, {%1, %2};" : "=l"(r) : "f"(lo), "f"(hi)); return r;
}
__device__ __forceinline__ void upk2(u64 v, float& lo, float& hi) {
    asm("mov.b64 {%0, %1}, %2;" : "=f"(lo), "=f"(hi) : "l"(v));
}
__device__ __forceinline__ void fma2(u64& d, u64 a, u64 b) {
    asm("fma.rn.f32x2 %0, %1, %2, %0;" : "+l"(d) : "l"(a), "l"(b));
}
__device__ __forceinline__ u64 mk_key(float d, int j) {
    u64 k; asm("mov.b64 %0, {%1, %2};" : "=l"(k) : "r"(j), "r"(__float_as_uint(d)));
    return k;
}
__device__ __forceinline__ float selu_f(float x) {
    const float sc = 1.0507009873554805f;
    const float sa = 1.7580993408473766f;  // sc * alpha
    float e   = __expf(x);
    float neg = __fmaf_rn(sa, e, -sa);
    return x > 0.f ? sc * x : neg;
}
__device__ __forceinline__ void cpa16(u32 dst, const void* src) {
    asm volatile("cp.async.cg.shared.global [%0], [%1], 16;" :: "r"(dst), "l"(src));
}
__device__ __forceinline__ u32 smem_u32(const void* p) {
    u32 a; asm("{ .reg .u64 t; cvta.to.shared.u64 t, %1; cvt.u32.u64 %0, t; }" : "=r"(a) : "l"(p));
    return a;
}
// pack two f32 -> bf16x2 (low half = x0, high half = x1)
__device__ __forceinline__ u32 pack2bf(float x0, float x1) {
    u32 r; asm("cvt.rn.bf16x2.f32 %0, %1, %2;" : "=r"(r) : "f"(x1), "f"(x0)); return r;
}
// bf16 mma m16n8k16, f32 accumulate
__device__ __forceinline__ void hmma(float (&d)[4], u32 a0, u32 a1, u32 a2, u32 a3,
                                     u32 b0, u32 b1) {
    asm volatile(
        "mma.sync.aligned.m16n8k16.row.col.f32.bf16.bf16.f32 "
        "{%0,%1,%2,%3}, {%4,%5,%6,%7}, {%8,%9}, {%0,%1,%2,%3};"
        : "+f"(d[0]), "+f"(d[1]), "+f"(d[2]), "+f"(d[3])
        : "r"(a0), "r"(a1), "r"(a2), "r"(a3), "r"(b0), "r"(b1));
}

// ---------------- merged prep: coords SoA + all weight images ----------------
__device__ __forceinline__ void wimg_body(const float* __restrict__ W, int K, int roff,
                                          u16* __restrict__ hi, u16* __restrict__ lo,
                                          int idx) {
    if (idx < K * 128) {
        int n = idx / K, k = idx - n * K;
        float v = W[(roff + k) * 128 + n];
        u32 ph = pack2bf(v, 0.f);
        float vh = __uint_as_float(ph << 16);
        u32 pl = pack2bf(v - vh, 0.f);
        hi[idx] = (u16)(ph & 0xffffu);
        lo[idx] = (u16)(pl & 0xffffu);
    }
}

// grid = CB + 352 blocks:
// [0,CB): coords SoA; [CB,+32): gW1s; [+32,+32): We1 img; [+64,+64): We2 img;
// [+128,+64): Wc1 img; [+192,+96): Wn1 img; [+288,+64): Wn2 img
__global__ void prep_all(const float* __restrict__ coords, int N, int CB,
                         const float* __restrict__ We1,
                         const float* __restrict__ We2,
                         const float* __restrict__ Wc1,
                         const float* __restrict__ Wn1,
                         const float* __restrict__ Wn2) {
    int b = blockIdx.x, tid = threadIdx.x;
    if (b < CB) {
        int i = b * 256 + tid;
        if (i < N) {
            float x = coords[3 * i + 0];
            float y = coords[3 * i + 1];
            float z = coords[3 * i + 2];
            g_sx[i] = x; g_sy[i] = y; g_sz[i] = z;
            g_sn[i] = __fmaf_rn(z, z, __fmaf_rn(y, y, __fmul_rn(x, x)));
        }
        return;
    }
    int r = b - CB;
    if (r < 32) {
        int i = r * 256 + tid;
        int k = i >> 7, n = i & 127;
        gW1s[i] = We1[(1 + k) * 128 + n];
    } else if (r < 64) {
        wimg_body(We1, 64, 65, gWh1, gWl1, (r - 32) * 256 + tid);
    } else if (r < 128) {
        wimg_body(We2, 128, 0, gWh2, gWl2, (r - 64) * 256 + tid);
    } else if (r < 192) {
        wimg_body(Wc1, 128, 0, gWh3, gWl3, (r - 128) * 256 + tid);
    } else if (r < 288) {
        wimg_body(Wn1, 192, 0, gWn1h, gWn1l, (r - 192) * 256 + tid);
    } else {
        wimg_body(Wn2, 128, 0, gWn2h, gWn2l, (r - 288) * 256 + tid);
    }
}

// ---------------- KNN: warp-distributed sorted top-17 (R13 verbatim) --------
#define KNN_WARPS 8
#define KSENT 0x7F800000FFFFFFFFull   // +inf distance sentinel

__global__ void __launch_bounds__(256)
knn_kernel(const int* __restrict__ rs, int nrs, int N,
           float* __restrict__ out_nidx_f, float* __restrict__ out_d)
{
    const int w    = threadIdx.x >> 5;
    const int lane = threadIdx.x & 31;
    const int row  = blockIdx.x * KNN_WARPS + w;
    (void)w;
    if (row >= N) return;

    int s0 = 0, s1 = N;
    for (int s = 0; s + 1 < nrs; ++s) {
        int a_ = rs[s], b_ = rs[s + 1];
        if (a_ <= row && row < b_) { s0 = a_; s1 = b_; }
    }

    const float xi = g_sx[row], yi = g_sy[row], zi = g_sz[row], ni = g_sn[row];

    u64 L    = KSENT;                           // warp-distributed list entry
    u64 curT = KSENT;                           // current 17th-smallest (L[16])
    float Tf = __uint_as_float(0x7F800000u);    // +inf

    auto insert_key = [&](u64 k) {
        unsigned bal = __ballot_sync(0xffffffffu, L <= k);
        int pos = __popc(bal);                  // <= 16 since k < L[16]
        u64 up = __shfl_up_sync(0xffffffffu, L, 1);
        if (lane == pos)                 L = k;
        else if (lane > pos && lane < 17) L = up;
        curT = __shfl_sync(0xffffffffu, L, 16);
        Tf = __uint_as_float((u32)(curT >> 32));
    };

    auto commit = [&](u64 key, bool pass) {
        unsigned pb = __ballot_sync(0xffffffffu, pass);
        while (pb) {
            int src = __ffs(pb) - 1; pb &= pb - 1;
            u64 k = __shfl_sync(0xffffffffu, key, src);
            if (k < curT) insert_key(k);        // warp-uniform branch
        }
    };

    auto d2_of = [&](float xj, float yj, float zj, float nj) {
        float dot = __fmul_rn(xi, xj);
        dot = __fmaf_rn(yi, yj, dot);
        dot = __fmaf_rn(zi, zj, dot);
        float nn = __fadd_rn(ni, nj);
        float d2 = __fmaf_rn(-2.f, dot, nn);
        return fmaxf(d2, 0.f);
    };

    // ---- prolog: align to 4 ----
    int jb = (s0 + 3) & ~3;
    if (jb > s1) jb = s1;
    {
        int pre = jb - s0;                      // 0..3
        bool act = lane < pre;
        int j = s0 + (act ? lane : 0);
        float d2 = d2_of(g_sx[j], g_sy[j], g_sz[j], g_sn[j]);
        u64 key = mk_key(d2, j);
        commit(key, act && d2 <= Tf);
    }

    const int nquad = (s1 - jb) >> 2;
    const int rem   = (s1 - jb) & 3;

    // ---- main quad loop: all lanes iterate together ----
    for (int q0 = 0; q0 < nquad; q0 += 32) {
        int q = q0 + lane;
        bool act = q < nquad;
        int j = jb + 4 * (act ? q : 0);
        float4 X  = *(const float4*)(g_sx + j);
        float4 Y  = *(const float4*)(g_sy + j);
        float4 Z  = *(const float4*)(g_sz + j);
        float4 Nn = *(const float4*)(g_sn + j);
        float xs[4] = {X.x, X.y, X.z, X.w};
        float ys[4] = {Y.x, Y.y, Y.z, Y.w};
        float zs[4] = {Z.x, Z.y, Z.z, Z.w};
        float ns[4] = {Nn.x, Nn.y, Nn.z, Nn.w};
#pragma unroll
        for (int c = 0; c < 4; ++c) {
            float d2 = d2_of(xs[c], ys[c], zs[c], ns[c]);
            u64 key = mk_key(d2, j + c);
            commit(key, act && d2 <= Tf);
        }
    }

    // ---- remainder ----
    if (rem) {
        bool act = lane < rem;
        int j = jb + 4 * nquad + (act ? lane : 0);
        float d2 = d2_of(g_sx[j], g_sy[j], g_sz[j], g_sn[j]);
        u64 key = mk_key(d2, j);
        commit(key, act && d2 <= Tf);
    }

    // ---- emit: lanes 0..16 hold the sorted top-17 ----
    if (lane < 17) {
        u32 jj = (u32)(L & 0xffffffffu);
        float dd = __uint_as_float((u32)(L >> 32));
        if (lane == 0) {
            g_selfi[row] = (int)jj;
        } else {
            int t = lane - 1;
            g_nidx[row * KNBR + t] = (int)jj;
            g_dsq [row * KNBR + t] = dd;
            out_nidx_f[row * KNBR + t] = (float)(int)jj;
            out_d    [row * KNBR + t] = dd;
        }
    }
}

// gNself[n] = h[self(n)] fp32 (for Yself stage); node-input image cols 128:192 = h_self hi/lo
__global__ void build_ns(const float* __restrict__ h, int N) {
    int idx = blockIdx.x * 256 + threadIdx.x;
    if (idx < N * 16) {
        int n = idx >> 4, q = idx & 15;
        float4 v = *(const float4*)(h + (size_t)g_selfi[n] * FDIM + q * 4);
        *(float4*)(gNself + (size_t)n * 64 + q * 4) = v;
        u32 ph0 = pack2bf(v.x, v.y);
        u32 ph1 = pack2bf(v.z, v.w);
        float a0 = __uint_as_float(ph0 << 16), a1 = __uint_as_float(ph0 & 0xffff0000u);
        float a2 = __uint_as_float(ph1 << 16), a3 = __uint_as_float(ph1 & 0xffff0000u);
        u32 pl0 = pack2bf(v.x - a0, v.y - a1);
        u32 pl1 = pack2bf(v.z - a2, v.w - a3);
        size_t off = (size_t)n * 192 + 128 + q * 4;
        *(u32*)(gNinh + off)     = ph0;  *(u32*)(gNinh + off + 2) = ph1;
        *(u32*)(gNinl + off)     = pl0;  *(u32*)(gNinl + off + 2) = pl1;
    }
}

// coords_new = coords + mean_k((c_i - c_j) * w)
__global__ void coords_kernel(const float* __restrict__ coords,
                              float* __restrict__ cout, int N) {
    int n = blockIdx.x * 256 + threadIdx.x;
    if (n < N) {
        float cx = coords[n * 3 + 0];
        float cy = coords[n * 3 + 1];
        float cz = coords[n * 3 + 2];
        float sx = 0.f, sy = 0.f, sz = 0.f;
#pragma unroll
        for (int k = 0; k < 16; ++k) {
            int j = g_nidx[n * 16 + k];
            float wv = g_w[n * 16 + k];
            sx += (cx - coords[j * 3 + 0]) * wv;
            sy += (cy - coords[j * 3 + 1]) * wv;
            sz += (cz - coords[j * 3 + 2]) * wv;
        }
        cout[n * 3 + 0] = cx + sx * 0.0625f;
        cout[n * 3 + 1] = cy + sy * 0.0625f;
        cout[n * 3 + 2] = cz + sz * 0.0625f;
    }
}

// ---------------- R5 FFMA staged GEMM (Yself; proven) ----------------
__device__ __forceinline__ void mma_chunk8(const float* __restrict__ As,
                                           const float* __restrict__ Ws,
                                           u64 (&acc)[8][4], int m0, int n0)
{
#pragma unroll
    for (int s = 0; s < 4; ++s) {
        float4 av[8];
#pragma unroll
        for (int i = 0; i < 8; ++i)
            av[i] = *(const float4*)(As + (m0 + i) * 16 + s * 4);
#pragma unroll
        for (int r = 0; r < 4; ++r) {
            const float* wr = Ws + (s * 4 + r) * 128 + n0;
            ulonglong2 b0 = *(const ulonglong2*)wr;
            ulonglong2 b1 = *(const ulonglong2*)(wr + 4);
#pragma unroll
            for (int i = 0; i < 8; ++i) {
                float a_ = (r == 0) ? av[i].x : (r == 1) ? av[i].y : (r == 2) ? av[i].z : av[i].w;
                u64 aa = pk2(a_, a_);
                fma2(acc[i][0], aa, b0.x);
                fma2(acc[i][1], aa, b0.y);
                fma2(acc[i][2], aa, b1.x);
                fma2(acc[i][3], aa, b1.y);
            }
        }
    }
}

template<int KCH, int EPI>   // EPI: 0 = selu+store, 1 = store
__global__ void __launch_bounds__(256, 2)
gemm_stage(const float* __restrict__ A, int lda,
           const float* __restrict__ Wg, const float* __restrict__ bias,
           float* __restrict__ O, int ldo, int M)
{
    extern __shared__ float sm[];
    float* Ws = sm;
    float* As = Ws + KCH * 2048;
    float* sb = As + 4096;

    const int tid = threadIdx.x;
    const int tx = tid & 15, ty = tid >> 4;
    const int n0 = tx * 8,   m0 = ty * 8;
    const long row0 = (long)blockIdx.x * 128;

    for (int i = tid; i < KCH * 512; i += 256)
        ((float4*)Ws)[i] = ((const float4*)Wg)[i];
    if (tid < 32) ((float4*)sb)[tid] = ((const float4*)bias)[tid];

    const u32 asu = (u32)__cvta_generic_to_shared(As);
    auto issue = [&](int c, int bufsel) {
        const float* srcbase = A + row0 * lda + c * 16;
        u32 d0 = asu + (u32)(bufsel * 2048 * 4);
        int q = tid;   int r = q >> 2, kq = q & 3;
        cpa16(d0 + (u32)((r * 16 + kq * 4) * 4), srcbase + (long)r * lda + kq * 4);
        q = tid + 256; r = q >> 2; kq = q & 3;
        cpa16(d0 + (u32)((r * 16 + kq * 4) * 4), srcbase + (long)r * lda + kq * 4);
        asm volatile("cp.async.commit_group;");
    };

    issue(0, 0);
    __syncthreads();

    u64 acc[8][4];
#pragma unroll
    for (int i = 0; i < 8; ++i)
#pragma unroll
        for (int j = 0; j < 4; ++j)
            acc[i][j] = pk2(sb[n0 + 2 * j], sb[n0 + 2 * j + 1]);

#pragma unroll 1
    for (int c = 0; c < KCH; ++c) {
        if (c + 1 < KCH) {
            issue(c + 1, (c + 1) & 1);
            asm volatile("cp.async.wait_group 1;");
        } else {
            asm volatile("cp.async.wait_group 0;");
        }
        __syncthreads();
        mma_chunk8(As + (c & 1) * 2048, Ws + c * 2048, acc, m0, n0);
        __syncthreads();
    }

#pragma unroll
    for (int i = 0; i < 8; ++i) {
        long grow = row0 + m0 + i;
        if (grow < M) {
            float o[8];
#pragma unroll
            for (int j = 0; j < 4; ++j) upk2(acc[i][j], o[2 * j], o[2 * j + 1]);
            if (EPI == 0) {
#pragma unroll
                for (int j = 0; j < 8; ++j) o[j] = selu_f(o[j]);
            }
            *(float4*)(O + grow * ldo + n0)     = make_float4(o[0], o[1], o[2], o[3]);
            *(float4*)(O + grow * ldo + n0 + 4) = make_float4(o[4], o[5], o[6], o[7]);
        }
    }
}

// ---------------- fused edge stage 1: gather h_neig + HMMA (KK=64) ----------
__global__ void __launch_bounds__(256)
mma_stage1(const float* __restrict__ h,
           const u16* __restrict__ Wih, const u16* __restrict__ Wil,
           const float* __restrict__ aux,     // We1 row 0
           const float* __restrict__ yselfg,
           const float* __restrict__ dsqg,
           u16* __restrict__ outHi, u16* __restrict__ outLo)
{
    constexpr int KK = 64;
    constexpr int SA = KK + 8;
    extern __shared__ u16 smu[];
    u16* sAh = smu;
    u16* sAl = sAh + 128 * SA;
    u16* sWh = sAl + 128 * SA;
    u16* sWl = sWh + 128 * SA;

    const int tid  = threadIdx.x;
    const int w    = tid >> 5;
    const int lane = tid & 31;
    const int g    = lane >> 2;
    const int tig  = lane & 3;
    const int tile = blockIdx.x;

    // ---- W copies via cp.async (overlap with A gather) ----
    const u32 sb = smem_u32(smu);
    for (int i = tid; i < 1024; i += 256) {        // 128 rows x 8 chunks
        int r = i >> 3, c = i & 7;
        u32 dof = (u32)((r * SA + c * 8) * 2);
        u32 sof = (u32)((r * KK + c * 8) * 2);
        cpa16(sb + 2 * 128 * SA * 2 + dof, (const char*)Wih + sof);
        cpa16(sb + 3 * 128 * SA * 2 + dof, (const char*)Wil + sof);
    }
    asm volatile("cp.async.commit_group;");

    // ---- A gather: 2 threads per row, 32 floats each ----
    {
        int r  = tid >> 1;
        int hf = tid & 1;
        int nb = g_nidx[tile * 128 + r];
        const float* hr = h + (size_t)nb * FDIM + hf * 32;
        u16* dh = sAh + r * SA + hf * 32;
        u16* dl = sAl + r * SA + hf * 32;
#pragma unroll
        for (int c = 0; c < 4; ++c) {
            float4 f0 = *(const float4*)(hr + c * 8);
            float4 f1 = *(const float4*)(hr + c * 8 + 4);
            float x[8] = {f0.x, f0.y, f0.z, f0.w, f1.x, f1.y, f1.z, f1.w};
            u32 hp[4], lp[4];
#pragma unroll
            for (int q = 0; q < 4; ++q) {
                u32 ph = pack2bf(x[2 * q], x[2 * q + 1]);
                float h0 = __uint_as_float(ph << 16);
                float h1 = __uint_as_float(ph & 0xffff0000u);
                hp[q] = ph;
                lp[q] = pack2bf(x[2 * q] - h0, x[2 * q + 1] - h1);
            }
            *(uint4*)(dh + c * 8) = make_uint4(hp[0], hp[1], hp[2], hp[3]);
            *(uint4*)(dl + c * 8) = make_uint4(lp[0], lp[1], lp[2], lp[3]);
        }
    }

    // ---- accumulator init (zero; bias folded via Yself) ----
    float acc[16][4];
#pragma unroll
    for (int nt = 0; nt < 16; ++nt) {
        acc[nt][0] = 0.f; acc[nt][1] = 0.f; acc[nt][2] = 0.f; acc[nt][3] = 0.f;
    }

    asm volatile("cp.async.wait_group 0;");
    __syncthreads();

    const int rA0 = (16 * w + g) * SA;
    const int rA1 = (16 * w + g + 8) * SA;

#pragma unroll
    for (int k0 = 0; k0 < KK; k0 += 16) {
        const int co = k0 + 2 * tig;
        u32 ah0 = *(const u32*)(sAh + rA0 + co);
        u32 ah1 = *(const u32*)(sAh + rA1 + co);
        u32 ah2 = *(const u32*)(sAh + rA0 + co + 8);
        u32 ah3 = *(const u32*)(sAh + rA1 + co + 8);
        u32 al0 = *(const u32*)(sAl + rA0 + co);
        u32 al1 = *(const u32*)(sAl + rA1 + co);
        u32 al2 = *(const u32*)(sAl + rA0 + co + 8);
        u32 al3 = *(const u32*)(sAl + rA1 + co + 8);
#pragma unroll
        for (int nt = 0; nt < 16; ++nt) {
            const int rb = (nt * 8 + g) * SA + co;
            u32 bh0 = *(const u32*)(sWh + rb);
            u32 bh1 = *(const u32*)(sWh + rb + 8);
            u32 bl0 = *(const u32*)(sWl + rb);
            u32 bl1 = *(const u32*)(sWl + rb + 8);
            hmma(acc[nt], ah0, ah1, ah2, ah3, bh0, bh1);
            hmma(acc[nt], ah0, ah1, ah2, ah3, bl0, bl1);
            hmma(acc[nt], al0, al1, al2, al3, bh0, bh1);
        }
    }

    // ---- epilogue (EPI1) ----
    const int node = tile * 8 + w;
    float dsq_r[2];
    dsq_r[0] = dsqg[(size_t)tile * 128 + 16 * w + g];
    dsq_r[1] = dsqg[(size_t)tile * 128 + 16 * w + g + 8];

#pragma unroll
    for (int nt = 0; nt < 16; ++nt) {
        const int col = nt * 8 + 2 * tig;
        float2 t = *(const float2*)(yselfg + (size_t)node * 128 + col);
        float2 u = *(const float2*)(aux + col);
#pragma unroll
        for (int r = 0; r < 2; ++r) {
            const int row = 16 * w + g + 8 * r;
            const size_t gr = (size_t)tile * 128 + row;
            float v0 = acc[nt][2 * r]     + t.x + dsq_r[r] * u.x;
            float v1 = acc[nt][2 * r + 1] + t.y + dsq_r[r] * u.y;
            v0 = selu_f(v0); v1 = selu_f(v1);
            u32 ph = pack2bf(v0, v1);
            float h0 = __uint_as_float(ph << 16);
            float h1 = __uint_as_float(ph & 0xffff0000u);
            u32 pl = pack2bf(v0 - h0, v1 - h1);
            *(u32*)((char*)outHi + (gr * 128 + col) * 2) = ph;
            *(u32*)((char*)outLo + (gr * 128 + col) * 2) = pl;
        }
    }
}

// ---------------- HMMA GEMM stage (bf16 hi/lo 3-term split) ----------------
// EPI: 0 = bias+selu, emit bf16 images                       (node stage 1)
//      2 = bias+selu, emit bf16 images, e_sum -> esum images (edge stage 2)
//      3 = bias+selu, dot with Wc2 -> g_w                    (edge stage 3)
//      5 = bias, fp32 store (bounds-checked)                 (node stage 2)
template<int KK, int EPI>
__global__ void __launch_bounds__(256)
mma_stage(const u16* __restrict__ Aih, const u16* __restrict__ Ail,
          const u16* __restrict__ Wih, const u16* __restrict__ Wil,
          const float* __restrict__ biasg,
          const float* __restrict__ aux,     // EPI3: Wc2
          const float* __restrict__ bc2g,    // EPI3
          u16* __restrict__ outHi, u16* __restrict__ outLo,   // EPI 0/2
          u16* __restrict__ esumHi, u16* __restrict__ esumLo, // EPI2
          float* __restrict__ woutg,         // EPI3
          float* __restrict__ Og, int M)     // EPI5
{
    constexpr int SA = KK + 8;
    extern __shared__ u16 smu[];
    u16* sAh = smu;
    u16* sAl = sAh + 128 * SA;
    u16* sWh = sAl + 128 * SA;
    u16* sWl = sWh + 128 * SA;

    const int tid  = threadIdx.x;
    const int w    = tid >> 5;
    const int lane = tid & 31;
    const int g    = lane >> 2;
    const int tig  = lane & 3;
    const int tile = blockIdx.x;

    // ---- async copies: two commit groups, split by K-halves ----
    constexpr int CPR = KK / 8;
    constexpr int HC  = CPR / 2;
    const u32 sb = smem_u32(smu);
    {
        const char* sa = (const char*)Aih + (size_t)tile * 128 * KK * 2;
        const char* sl = (const char*)Ail + (size_t)tile * 128 * KK * 2;
#pragma unroll
        for (int hh = 0; hh < 2; ++hh) {
            for (int i = tid; i < 128 * HC; i += 256) {
                int r = i / HC, c = hh * HC + (i - (i / HC) * HC);
                u32 dof = (u32)((r * SA + c * 8) * 2);
                u32 sof = (u32)((r * KK + c * 8) * 2);
                cpa16(sb + dof,                   sa + sof);
                cpa16(sb + 128 * SA * 2 + dof,    sl + sof);
                cpa16(sb + 2 * 128 * SA * 2 + dof, (const char*)Wih + sof);
                cpa16(sb + 3 * 128 * SA * 2 + dof, (const char*)Wil + sof);
            }
            asm volatile("cp.async.commit_group;");
        }
    }

    // ---- accumulator init (bias) ----
    float acc[16][4];
#pragma unroll
    for (int nt = 0; nt < 16; ++nt) {
        float b0 = __ldg(biasg + nt * 8 + 2 * tig);
        float b1 = __ldg(biasg + nt * 8 + 2 * tig + 1);
        acc[nt][0] = b0; acc[nt][1] = b1; acc[nt][2] = b0; acc[nt][3] = b1;
    }

    const int rA0 = (16 * w + g) * SA;
    const int rA1 = (16 * w + g + 8) * SA;

    auto mma_k = [&](int k0) {
        const int co = k0 + 2 * tig;
        u32 ah0 = *(const u32*)(sAh + rA0 + co);
        u32 ah1 = *(const u32*)(sAh + rA1 + co);
        u32 ah2 = *(const u32*)(sAh + rA0 + co + 8);
        u32 ah3 = *(const u32*)(sAh + rA1 + co + 8);
        u32 al0 = *(const u32*)(sAl + rA0 + co);
        u32 al1 = *(const u32*)(sAl + rA1 + co);
        u32 al2 = *(const u32*)(sAl + rA0 + co + 8);
        u32 al3 = *(const u32*)(sAl + rA1 + co + 8);
#pragma unroll
        for (int nt = 0; nt < 16; ++nt) {
            const int rb = (nt * 8 + g) * SA + co;
            u32 bh0 = *(const u32*)(sWh + rb);
            u32 bh1 = *(const u32*)(sWh + rb + 8);
            u32 bl0 = *(const u32*)(sWl + rb);
            u32 bl1 = *(const u32*)(sWl + rb + 8);
            hmma(acc[nt], ah0, ah1, ah2, ah3, bh0, bh1);
            hmma(acc[nt], ah0, ah1, ah2, ah3, bl0, bl1);
            hmma(acc[nt], al0, al1, al2, al3, bh0, bh1);
        }
    };

    asm volatile("cp.async.wait_group 1;");
    __syncthreads();
#pragma unroll
    for (int k0 = 0; k0 < KK / 2; k0 += 16) mma_k(k0);

    asm volatile("cp.async.wait_group 0;");
    __syncthreads();
#pragma unroll
    for (int k0 = KK / 2; k0 < KK; k0 += 16) mma_k(k0);

    // ---- epilogue ----
    const int node = tile * 8 + w;
    float pr[2] = {0.f, 0.f};

#pragma unroll
    for (int nt = 0; nt < 16; ++nt) {
        const int col = nt * 8 + 2 * tig;
        float wv0 = 0.f, wv1 = 0.f;
        if (EPI == 3) {
            float2 u = *(const float2*)(aux + col);
            wv0 = u.x; wv1 = u.y;
        }
        float ps0 = 0.f, ps1 = 0.f;
#pragma unroll
        for (int r = 0; r < 2; ++r) {
            const int row = 16 * w + g + 8 * r;
            const size_t gr = (size_t)tile * 128 + row;
            float v0 = acc[nt][2 * r];
            float v1 = acc[nt][2 * r + 1];
            if (EPI != 5) { v0 = selu_f(v0); v1 = selu_f(v1); }
            if (EPI == 0 || EPI == 2) {
                u32 ph = pack2bf(v0, v1);
                float h0 = __uint_as_float(ph << 16);
                float h1 = __uint_as_float(ph & 0xffff0000u);
                u32 pl = pack2bf(v0 - h0, v1 - h1);
                *(u32*)((char*)outHi + (gr * 128 + col) * 2) = ph;
                *(u32*)((char*)outLo + (gr * 128 + col) * 2) = pl;
            }
            if (EPI == 2) { ps0 += v0; ps1 += v1; }
            if (EPI == 3) { pr[r] = fmaf(v0, wv0, fmaf(v1, wv1, pr[r])); }
            if (EPI == 5) {
                if ((long)gr < M)
                    *(float2*)(Og + gr * 128 + col) = make_float2(v0, v1);
            }
        }
        if (EPI == 2) {
            ps0 += __shfl_xor_sync(0xffffffffu, ps0, 4);
            ps0 += __shfl_xor_sync(0xffffffffu, ps0, 8);
            ps0 += __shfl_xor_sync(0xffffffffu, ps0, 16);
            ps1 += __shfl_xor_sync(0xffffffffu, ps1, 4);
            ps1 += __shfl_xor_sync(0xffffffffu, ps1, 8);
            ps1 += __shfl_xor_sync(0xffffffffu, ps1, 16);
            if (g == 0) {
                u32 ph = pack2bf(ps0, ps1);
                float h0 = __uint_as_float(ph << 16);
                float h1 = __uint_as_float(ph & 0xffff0000u);
                u32 pl = pack2bf(ps0 - h0, ps1 - h1);
                size_t off = ((size_t)node * 192 + col) * 2;
                *(u32*)((char*)esumHi + off) = ph;
                *(u32*)((char*)esumLo + off) = pl;
            }
        }
    }
    if (EPI == 3) {
        const float bc = bc2g[0];
#pragma unroll
        for (int r = 0; r < 2; ++r) {
            float p = pr[r];
            p += __shfl_xor_sync(0xffffffffu, p, 1);
            p += __shfl_xor_sync(0xffffffffu, p, 2);
            if (tig == 0)
                woutg[(size_t)tile * 128 + 16 * w + g + 8 * r] = p + bc;
        }
    }
}

// ---------------- launch ----------------
extern "C" void kernel_launch(void* const* d_in, const int* in_sizes, int n_in,
                              void* d_out, int out_size)
{
    const float* h      = (const float*)d_in[0];
    const float* coords = (const float*)d_in[1];
    const int*   rs     = (const int*)  d_in[2];
    const float* We1 = (const float*)d_in[3];
    const float* be1 = (const float*)d_in[4];
    const float* We2 = (const float*)d_in[5];
    const float* be2 = (const float*)d_in[6];
    const float* Wc1 = (const float*)d_in[7];
    const float* bc1 = (const float*)d_in[8];
    const float* Wc2 = (const float*)d_in[9];
    const float* bc2 = (const float*)d_in[10];
    const float* Wn1 = (const float*)d_in[11];
    const float* bn1 = (const float*)d_in[12];
    const float* Wn2 = (const float*)d_in[13];
    const float* bn2 = (const float*)d_in[14];

    const int N   = in_sizes[1] / 3;
    const int nrs = in_sizes[2];
    const int E   = N * KNBR;
    const int tiles  = E / 128;
    const int ntiles = (N + 127) / 128;
    const int CB     = (N + 255) / 256;

    float* out        = (float*)d_out;               // [N,128]
    float* coords_out = out + (size_t)N * HDIM;      // [N,3]
    float* out_nidx   = coords_out + (size_t)N * 3;  // [N,16]
    float* out_d      = out_nidx + (size_t)N * KNBR; // [N,16]

    float *pW1s, *pNself, *pYself, *pw, *pdsq;
    u16 *pB2h, *pB2l, *pC3h, *pC3l;
    u16 *pWh1, *pWl1, *pWh2, *pWl2, *pWh3, *pWl3;
    u16 *pNinh, *pNinl, *pXn1h, *pXn1l, *pWn1h, *pWn1l, *pWn2h, *pWn2l;
    cudaGetSymbolAddress((void**)&pW1s,   gW1s);
    cudaGetSymbolAddress((void**)&pNself, gNself);
    cudaGetSymbolAddress((void**)&pYself, gYself);
    cudaGetSymbolAddress((void**)&pw,     g_w);
    cudaGetSymbolAddress((void**)&pdsq,   g_dsq);
    cudaGetSymbolAddress((void**)&pB2h, gB2h);  cudaGetSymbolAddress((void**)&pB2l, gB2l);
    cudaGetSymbolAddress((void**)&pC3h, gC3h);  cudaGetSymbolAddress((void**)&pC3l, gC3l);
    cudaGetSymbolAddress((void**)&pWh1, gWh1);  cudaGetSymbolAddress((void**)&pWl1, gWl1);
    cudaGetSymbolAddress((void**)&pWh2, gWh2);  cudaGetSymbolAddress((void**)&pWl2, gWl2);
    cudaGetSymbolAddress((void**)&pWh3, gWh3);  cudaGetSymbolAddress((void**)&pWl3, gWl3);
    cudaGetSymbolAddress((void**)&pNinh, gNinh); cudaGetSymbolAddress((void**)&pNinl, gNinl);
    cudaGetSymbolAddress((void**)&pXn1h, gXn1h); cudaGetSymbolAddress((void**)&pXn1l, gXn1l);
    cudaGetSymbolAddress((void**)&pWn1h, gWn1h); cudaGetSymbolAddress((void**)&pWn1l, gWn1l);
    cudaGetSymbolAddress((void**)&pWn2h, gWn2h); cudaGetSymbolAddress((void**)&pWn2l, gWn2l);

    const int SM4  = (4 * 2048 + 4096 + 256) * 4;
    const int SMM1 = 4 * 128 * (64 + 8) * 2;    // 73728
    const int SMM2 = 4 * 128 * (128 + 8) * 2;   // 139264
    const int SMN1 = 4 * 128 * (192 + 8) * 2;   // 204800
    cudaFuncSetAttribute(gemm_stage<4, 1>,  cudaFuncAttributeMaxDynamicSharedMemorySize, SM4);
    cudaFuncSetAttribute(mma_stage1,        cudaFuncAttributeMaxDynamicSharedMemorySize, SMM1);
    cudaFuncSetAttribute(mma_stage<128, 2>, cudaFuncAttributeMaxDynamicSharedMemorySize, SMM2);
    cudaFuncSetAttribute(mma_stage<128, 3>, cudaFuncAttributeMaxDynamicSharedMemorySize, SMM2);
    cudaFuncSetAttribute(mma_stage<192, 0>, cudaFuncAttributeMaxDynamicSharedMemorySize, SMN1);
    cudaFuncSetAttribute(mma_stage<128, 5>, cudaFuncAttributeMaxDynamicSharedMemorySize, SMM2);

    // merged prep (coords SoA + all weight images)
    prep_all<<<CB + 352, 256>>>(coords, N, CB, We1, We2, Wc1, Wn1, Wn2);
    knn_kernel<<<(N + KNN_WARPS - 1) / KNN_WARPS, 256>>>(rs, nrs, N, out_nidx, out_d);
    build_ns<<<(N * 16 + 255) / 256, 256>>>(h, N);

    // Yself = h_self @ We1[1:65] + be1   (pre-activation partial, fp32)
    gemm_stage<4, 1><<<ntiles, 256, SM4>>>(pNself, 64, pW1s, be1, pYself, 128, N);

    // edge MLP on HMMA (bf16 hi/lo split); stage 1 gathers h_neig in-kernel
    mma_stage1<<<tiles, 256, SMM1>>>(h, pWh1, pWl1, We1, pYself, pdsq, pB2h, pB2l);
    mma_stage<128, 2><<<tiles, 256, SMM2>>>(pB2h, pB2l, pWh2, pWl2,
                                            be2, nullptr, nullptr,
                                            pC3h, pC3l, pNinh, pNinl,
                                            nullptr, nullptr, 0);
    mma_stage<128, 3><<<tiles, 256, SMM2>>>(pC3h, pC3l, pWh3, pWl3,
                                            bc1, Wc2, bc2,
                                            nullptr, nullptr, nullptr, nullptr,
                                            pw, nullptr, 0);

    coords_kernel<<<(N + 255) / 256, 256>>>(coords, coords_out, N);

    // node MLP on HMMA
    mma_stage<192, 0><<<ntiles, 256, SMN1>>>(pNinh, pNinl, pWn1h, pWn1l,
                                             bn1, nullptr, nullptr,
                                             pXn1h, pXn1l, nullptr, nullptr,
                                             nullptr, nullptr, 0);
    mma_stage<128, 5><<<ntiles, 256, SMM2>>>(pXn1h, pXn1l, pWn2h, pWn2l,
                                             bn2, nullptr, nullptr,
                                             nullptr, nullptr, nullptr, nullptr,
                                             nullptr, out, N);
}